// round 2
// baseline (speedup 1.0000x reference)
#include <cuda_runtime.h>
#include <cstdint>

#define Bz   64
#define Lz   1024
#define Hz   512
#define HALFz 256
#define Vz   32000
#define Mz   (Bz*Lz)          /* 65536 rows */

// ---------------- scratch (device globals; no allocations allowed) ----------
__device__ float g_relu[(size_t)Mz * 1024];   // 256 MB  relu(e@W1+b1)
__device__ float g_x   [(size_t)Mz * Hz];     // 128 MB  e + ffn
__device__ float g_h   [(size_t)Mz * Hz];     // 128 MB  layernorm out
__device__ float g_ks  [(size_t)Mz * HALFz];  // 64 MB
__device__ float g_ke  [(size_t)Mz * HALFz];  // 64 MB
__device__ float g_sinv[2 * Mz];              // 1/(k.k+eps) for [ks|ke]
__device__ float g_c   [Bz * 2 * HALFz];      // concat(cs, ce) per batch

// ---------------- tiled FP32 GEMM --------------------------------------------
// MODE 0: A[m,k] = embed[seq[m]][k], epilogue relu(acc+bias) -> g_relu
// MODE 1: A = g_relu,                epilogue acc+bias+embed[seq[m]][n] -> g_x
// MODE 2: A = g_h,                   epilogue acc+bias -> (outsel? g_ke : g_ks)
template<int MODE>
__global__ __launch_bounds__(256)
void gemm_k(const int* __restrict__ seq, const float* __restrict__ embed,
            const float* __restrict__ Bm, const float* __restrict__ bias,
            int M, int N, int K, int outsel)
{
    constexpr int BM = 128, BN = 128, BK = 16;
    __shared__ float As[BK][BM];
    __shared__ float Bs[BK][BN];
    __shared__ int   seqs[BM];

    const int tid = threadIdx.x;
    const int m0 = blockIdx.y * BM;
    const int n0 = blockIdx.x * BN;

    if (MODE != 2) { if (tid < BM) seqs[tid] = seq[m0 + tid]; }

    const int am = tid >> 2;          // 0..63
    const int ak = (tid & 3) << 2;    // 0,4,8,12
    const int bk = tid >> 5;          // 0..7
    const int bn = (tid & 31) << 2;   // 0..124
    const int ty = tid >> 4;          // 0..15
    const int tx = tid & 15;          // 0..15

    const float* Ap;
    float* Cp;
    if (MODE == 0)      { Ap = nullptr; Cp = g_relu; }
    else if (MODE == 1) { Ap = g_relu;  Cp = g_x; }
    else                { Ap = g_h;     Cp = outsel ? g_ke : g_ks; }

    float acc[8][8];
    #pragma unroll
    for (int i = 0; i < 8; i++)
        #pragma unroll
        for (int j = 0; j < 8; j++) acc[i][j] = 0.f;

    __syncthreads();   // seqs visible

    for (int k0 = 0; k0 < K; k0 += BK) {
        #pragma unroll
        for (int p = 0; p < 2; p++) {
            int m = am + p * 64;
            const float* src;
            if (MODE == 0) src = embed + (size_t)seqs[m] * Hz + k0 + ak;
            else           src = Ap + (size_t)(m0 + m) * K + k0 + ak;
            float4 v = *(const float4*)src;
            As[ak + 0][m] = v.x; As[ak + 1][m] = v.y;
            As[ak + 2][m] = v.z; As[ak + 3][m] = v.w;
        }
        #pragma unroll
        for (int p = 0; p < 2; p++) {
            int kk = bk + p * 8;
            float4 v = *(const float4*)(Bm + (size_t)(k0 + kk) * N + n0 + bn);
            *(float4*)&Bs[kk][bn] = v;
        }
        __syncthreads();

        #pragma unroll
        for (int kk = 0; kk < BK; kk++) {
            float ra[8], rb[8];
            *(float4*)(ra)     = *(const float4*)&As[kk][ty * 8];
            *(float4*)(ra + 4) = *(const float4*)&As[kk][ty * 8 + 4];
            *(float4*)(rb)     = *(const float4*)&Bs[kk][tx * 8];
            *(float4*)(rb + 4) = *(const float4*)&Bs[kk][tx * 8 + 4];
            #pragma unroll
            for (int i = 0; i < 8; i++)
                #pragma unroll
                for (int j = 0; j < 8; j++) acc[i][j] += ra[i] * rb[j];
        }
        __syncthreads();
    }

    #pragma unroll
    for (int i = 0; i < 8; i++) {
        int m = m0 + ty * 8 + i;
        #pragma unroll
        for (int j = 0; j < 8; j += 4) {
            int n = n0 + tx * 8 + j;
            float4 r;
            r.x = acc[i][j + 0] + bias[n + 0];
            r.y = acc[i][j + 1] + bias[n + 1];
            r.z = acc[i][j + 2] + bias[n + 2];
            r.w = acc[i][j + 3] + bias[n + 3];
            if (MODE == 0) {
                r.x = fmaxf(r.x, 0.f); r.y = fmaxf(r.y, 0.f);
                r.z = fmaxf(r.z, 0.f); r.w = fmaxf(r.w, 0.f);
            }
            if (MODE == 1) {
                const float* e = embed + (size_t)seqs[ty * 8 + i] * Hz + n;
                r.x += e[0]; r.y += e[1]; r.z += e[2]; r.w += e[3];
            }
            *(float4*)(Cp + (size_t)m * N + n) = r;
        }
    }
}

// ---------------- LayerNorm: g_x -> g_h (one warp per row) -------------------
__global__ __launch_bounds__(256)
void ln_k(const float* __restrict__ gam, const float* __restrict__ bet)
{
    int row  = blockIdx.x * 8 + (threadIdx.x >> 5);
    int lane = threadIdx.x & 31;
    const float* x = g_x + (size_t)row * Hz;

    float4 v[4];
    float sum = 0.f, sq = 0.f;
    #pragma unroll
    for (int i = 0; i < 4; i++) {
        v[i] = *(const float4*)(x + lane * 4 + i * 128);
        sum += v[i].x + v[i].y + v[i].z + v[i].w;
        sq  += v[i].x * v[i].x + v[i].y * v[i].y + v[i].z * v[i].z + v[i].w * v[i].w;
    }
    #pragma unroll
    for (int off = 16; off > 0; off >>= 1) {
        sum += __shfl_xor_sync(0xffffffffu, sum, off);
        sq  += __shfl_xor_sync(0xffffffffu, sq,  off);
    }
    float mean = sum * (1.f / 512.f);
    float var  = sq  * (1.f / 512.f) - mean * mean;
    float rs   = rsqrtf(var + 1e-5f);

    float* o = g_h + (size_t)row * Hz;
    #pragma unroll
    for (int i = 0; i < 4; i++) {
        int col = lane * 4 + i * 128;
        float4 gg = *(const float4*)(gam + col);
        float4 bb = *(const float4*)(bet + col);
        float4 r;
        r.x = (v[i].x - mean) * rs * gg.x + bb.x;
        r.y = (v[i].y - mean) * rs * gg.y + bb.y;
        r.z = (v[i].z - mean) * rs * gg.z + bb.z;
        r.w = (v[i].w - mean) * rs * gg.w + bb.w;
        *(float4*)(o + col) = r;
    }
}

// ---------------- 1/(k.k + 1e-6): one warp per row ---------------------------
__global__ __launch_bounds__(256)
void sinv_k()
{
    int idx  = blockIdx.x * 8 + (threadIdx.x >> 5);   // 0 .. 2*Mz-1
    int lane = threadIdx.x & 31;
    const float* kp = (idx < Mz) ? (g_ks + (size_t)idx * HALFz)
                                 : (g_ke + (size_t)(idx - Mz) * HALFz);
    float s = 0.f;
    #pragma unroll
    for (int i = 0; i < 2; i++) {
        float4 v = *(const float4*)(kp + lane * 4 + i * 128);
        s += v.x * v.x + v.y * v.y + v.z * v.z + v.w * v.w;
    }
    #pragma unroll
    for (int off = 16; off > 0; off >>= 1)
        s += __shfl_xor_sync(0xffffffffu, s, off);
    if (lane == 0) g_sinv[idx] = 1.f / (s + 1e-6f);
}

// ---------------- delta-rule scan -------------------------------------------
// grid (8 rowblocks, 2 matrices, 64 batches), 256 threads.
// warp handles 4 rows; 8 lanes per row, 32 M-floats per lane (registers).
__global__ __launch_bounds__(256)
void scan_k()
{
    const int b   = blockIdx.z;
    const int mat = blockIdx.y;
    const int rb  = blockIdx.x;
    const float* kbase = (mat == 0 ? g_ks : g_ke) + (size_t)b * Lz * HALFz;
    const float* sv    = g_sinv + mat * Mz + b * Lz;

    const int warp = threadIdx.x >> 5;
    const int lane = threadIdx.x & 31;
    const int sub  = lane >> 3;     // row within warp group
    const int c    = lane & 7;      // 32-wide column chunk
    const int row  = rb * 32 + warp * 4 + sub;
    const int cb   = c * 32;

    float Mr[32];
    #pragma unroll
    for (int i = 0; i < 32; i++) Mr[i] = 0.f;

    for (int t = 0; t < Lz - 1; t++) {
        const float* kt = kbase + t * HALFz;
        float kr[32];
        #pragma unroll
        for (int q = 0; q < 8; q++) {
            float4 v = __ldg((const float4*)(kt + cb + q * 4));
            kr[q * 4 + 0] = v.x; kr[q * 4 + 1] = v.y;
            kr[q * 4 + 2] = v.z; kr[q * 4 + 3] = v.w;
        }
        float d0 = 0.f, d1 = 0.f, d2 = 0.f, d3 = 0.f;
        #pragma unroll
        for (int q = 0; q < 8; q++) {
            d0 += Mr[q * 4 + 0] * kr[q * 4 + 0];
            d1 += Mr[q * 4 + 1] * kr[q * 4 + 1];
            d2 += Mr[q * 4 + 2] * kr[q * 4 + 2];
            d3 += Mr[q * 4 + 3] * kr[q * 4 + 3];
        }
        float dot = (d0 + d1) + (d2 + d3);
        dot += __shfl_xor_sync(0xffffffffu, dot, 1, 8);
        dot += __shfl_xor_sync(0xffffffffu, dot, 2, 8);
        dot += __shfl_xor_sync(0xffffffffu, dot, 4, 8);

        float inv  = __ldg(sv + t);
        float krow = __ldg(kt + row);
        float d = krow - dot * inv;
        if (mat == 1) d *= (float)(t + 1) * (1.f / 1024.f);
        #pragma unroll
        for (int q = 0; q < 32; q++) Mr[q] += d * kr[q];
    }

    // final query: c = M . k_{L-1}
    {
        const float* kt = kbase + (size_t)(Lz - 1) * HALFz;
        float d0 = 0.f, d1 = 0.f, d2 = 0.f, d3 = 0.f;
        #pragma unroll
        for (int q = 0; q < 8; q++) {
            float4 v = __ldg((const float4*)(kt + cb + q * 4));
            d0 += Mr[q * 4 + 0] * v.x;
            d1 += Mr[q * 4 + 1] * v.y;
            d2 += Mr[q * 4 + 2] * v.z;
            d3 += Mr[q * 4 + 3] * v.w;
        }
        float dot = (d0 + d1) + (d2 + d3);
        dot += __shfl_xor_sync(0xffffffffu, dot, 1, 8);
        dot += __shfl_xor_sync(0xffffffffu, dot, 2, 8);
        dot += __shfl_xor_sync(0xffffffffu, dot, 4, 8);
        if (c == 0) g_c[b * (2 * HALFz) + mat * HALFz + row] = dot;
    }
}

// ---------------- logits: out = c @ out_w + out_b ---------------------------
// grid (125, 4): 256 n-columns x 16 m-rows per block.
__global__ __launch_bounds__(256)
void out_k(const float* __restrict__ W, const float* __restrict__ ob,
           float* __restrict__ out)
{
    __shared__ float sc[512][16];      // k-major so float4 over m works
    const int mt  = blockIdx.y;
    const int tid = threadIdx.x;

    for (int i = tid; i < 16 * 512; i += 256) {
        int mm = i >> 9, k = i & 511;
        sc[k][mm] = g_c[(mt * 16 + mm) * 512 + k];
    }
    __syncthreads();

    const int n = blockIdx.x * 256 + tid;
    float acc[16];
    #pragma unroll
    for (int m = 0; m < 16; m++) acc[m] = 0.f;

    #pragma unroll 8
    for (int k = 0; k < 512; k++) {
        float w = __ldg(W + (size_t)k * Vz + n);
        #pragma unroll
        for (int q = 0; q < 4; q++) {
            float4 s = *(const float4*)&sc[k][q * 4];
            acc[q * 4 + 0] += s.x * w;
            acc[q * 4 + 1] += s.y * w;
            acc[q * 4 + 2] += s.z * w;
            acc[q * 4 + 3] += s.w * w;
        }
    }
    float bb = ob[n];
    #pragma unroll
    for (int m = 0; m < 16; m++)
        out[(size_t)(mt * 16 + m) * Vz + n] = acc[m] + bb;
}

// ---------------- launch ------------------------------------------------------
extern "C" void kernel_launch(void* const* d_in, const int* in_sizes, int n_in,
                              void* d_out, int out_size)
{
    (void)in_sizes; (void)n_in; (void)out_size;
    const int*   seq    = (const int*)  d_in[0];
    const float* embed  = (const float*)d_in[1];
    const float* ff_w1  = (const float*)d_in[2];
    const float* ff_b1  = (const float*)d_in[3];
    const float* ff_w2  = (const float*)d_in[4];
    const float* ff_b2  = (const float*)d_in[5];
    const float* ln_g   = (const float*)d_in[6];
    const float* ln_b   = (const float*)d_in[7];
    const float* sem_w  = (const float*)d_in[8];
    const float* sem_b  = (const float*)d_in[9];
    const float* epi_w  = (const float*)d_in[10];
    const float* epi_b  = (const float*)d_in[11];
    const float* out_w  = (const float*)d_in[12];
    const float* out_b  = (const float*)d_in[13];
    float* out = (float*)d_out;

    // 1) relu(embed[seq] @ ff_w1 + b1) -> g_relu     [M=65536, N=1024, K=512]
    gemm_k<0><<<dim3(8, 512), 256>>>(seq, embed, ff_w1, ff_b1, Mz, 1024, 512, 0);
    // 2) g_relu @ ff_w2 + b2 + embed[seq] -> g_x     [M=65536, N=512, K=1024]
    gemm_k<1><<<dim3(4, 512), 256>>>(seq, embed, ff_w2, ff_b2, Mz, 512, 1024, 0);
    // 3) LayerNorm -> g_h
    ln_k<<<Mz / 8, 256>>>(ln_g, ln_b);
    // 4) projections -> g_ks, g_ke                   [M=65536, N=256, K=512]
    gemm_k<2><<<dim3(2, 512), 256>>>(seq, embed, sem_w, sem_b, Mz, 256, 512, 0);
    gemm_k<2><<<dim3(2, 512), 256>>>(seq, embed, epi_w, epi_b, Mz, 256, 512, 1);
    // 5) inverse squared norms
    sinv_k<<<(2 * Mz) / 8, 256>>>();
    // 6) delta-rule scan -> g_c
    scan_k<<<dim3(8, 2, 64), 256>>>();
    // 7) logits
    out_k<<<dim3(125, 4), 256>>>(out_w, out_b, out);
}

// round 3
// speedup vs baseline: 1.0683x; 1.0683x over previous
#include <cuda_runtime.h>
#include <cstdint>

#define Bz   64
#define Lz   1024
#define Hz   512
#define HALFz 256
#define Vz   32000
#define Mz   (Bz*Lz)          /* 65536 rows */

typedef unsigned long long ull;

// ---------------- f32x2 packed-math helpers (sm_103a FFMA2) ------------------
__device__ __forceinline__ void fma2(ull &d, ull a, ull b) {
    asm("fma.rn.f32x2 %0, %1, %2, %0;" : "+l"(d) : "l"(a), "l"(b));
}
__device__ __forceinline__ ull pk(float lo, float hi) {
    ull r; asm("mov.b64 %0, {%1, %2};" : "=l"(r) : "f"(lo), "f"(hi)); return r;
}
__device__ __forceinline__ float2 upk(ull v) {
    float2 r; asm("mov.b64 {%0, %1}, %2;" : "=f"(r.x), "=f"(r.y) : "l"(v)); return r;
}

// ---------------- scratch (device globals; no allocations allowed) ----------
__device__ float g_relu[(size_t)Mz * 1024];   // 256 MB  relu(e@W1+b1)
__device__ float g_x   [(size_t)Mz * Hz];     // 128 MB  e + ffn
__device__ float g_h   [(size_t)Mz * Hz];     // 128 MB  layernorm out
__device__ float g_ks  [(size_t)Mz * HALFz];  // 64 MB
__device__ float g_ke  [(size_t)Mz * HALFz];  // 64 MB
__device__ float g_sinv[2 * Mz];              // 1/(k.k+eps) for [ks|ke]
__device__ float g_c   [Bz * 2 * HALFz];      // concat(cs, ce) per batch

// ---------------- tiled FP32 GEMM (FFMA2 inner product) ----------------------
// MODE 0: A[m,k] = embed[seq[m]][k], epilogue relu(acc+bias) -> g_relu
// MODE 1: A = g_relu,                epilogue acc+bias+embed[seq[m]][n] -> g_x
// MODE 2: A = g_h,                   epilogue acc+bias -> (outsel? g_ke : g_ks)
template<int MODE>
__global__ __launch_bounds__(256)
void gemm_k(const int* __restrict__ seq, const float* __restrict__ embed,
            const float* __restrict__ Bm, const float* __restrict__ bias,
            int M, int N, int K, int outsel)
{
    constexpr int BM = 128, BN = 128, BK = 16;
    __shared__ float As[BK][BM];
    __shared__ float Bs[BK][BN];
    __shared__ int   seqs[BM];

    const int tid = threadIdx.x;
    const int m0 = blockIdx.y * BM;
    const int n0 = blockIdx.x * BN;

    if (MODE != 2) { if (tid < BM) seqs[tid] = seq[m0 + tid]; }

    const int am = tid >> 2;          // 0..63
    const int ak = (tid & 3) << 2;    // 0,4,8,12
    const int bk = tid >> 5;          // 0..7
    const int bn = (tid & 31) << 2;   // 0..124
    const int ty = tid >> 4;          // 0..15
    const int tx = tid & 15;          // 0..15

    const float* Ap;
    float* Cp;
    if (MODE == 0)      { Ap = nullptr; Cp = g_relu; }
    else if (MODE == 1) { Ap = g_relu;  Cp = g_x; }
    else                { Ap = g_h;     Cp = outsel ? g_ke : g_ks; }

    ull acc2[8][4];
    #pragma unroll
    for (int i = 0; i < 8; i++)
        #pragma unroll
        for (int j = 0; j < 4; j++) acc2[i][j] = 0ull;

    __syncthreads();   // seqs visible

    for (int k0 = 0; k0 < K; k0 += BK) {
        #pragma unroll
        for (int p = 0; p < 2; p++) {
            int m = am + p * 64;
            const float* src;
            if (MODE == 0) src = embed + (size_t)seqs[m] * Hz + k0 + ak;
            else           src = Ap + (size_t)(m0 + m) * K + k0 + ak;
            float4 v = *(const float4*)src;
            As[ak + 0][m] = v.x; As[ak + 1][m] = v.y;
            As[ak + 2][m] = v.z; As[ak + 3][m] = v.w;
        }
        #pragma unroll
        for (int p = 0; p < 2; p++) {
            int kk = bk + p * 8;
            float4 v = *(const float4*)(Bm + (size_t)(k0 + kk) * N + n0 + bn);
            *(float4*)&Bs[kk][bn] = v;
        }
        __syncthreads();

        #pragma unroll
        for (int kk = 0; kk < BK; kk++) {
            float ra[8];
            ull rb2[4];
            *(float4*)(ra)     = *(const float4*)&As[kk][ty * 8];
            *(float4*)(ra + 4) = *(const float4*)&As[kk][ty * 8 + 4];
            #pragma unroll
            for (int j = 0; j < 4; j++)
                rb2[j] = *(const ull*)&Bs[kk][tx * 8 + 2 * j];
            #pragma unroll
            for (int i = 0; i < 8; i++) {
                ull ra2 = pk(ra[i], ra[i]);
                #pragma unroll
                for (int j = 0; j < 4; j++) fma2(acc2[i][j], ra2, rb2[j]);
            }
        }
        __syncthreads();
    }

    #pragma unroll
    for (int i = 0; i < 8; i++) {
        int m = m0 + ty * 8 + i;
        float r[8];
        #pragma unroll
        for (int j = 0; j < 4; j++) {
            float2 t = upk(acc2[i][j]);
            r[2 * j] = t.x; r[2 * j + 1] = t.y;
        }
        #pragma unroll
        for (int j = 0; j < 8; j += 4) {
            int n = n0 + tx * 8 + j;
            float4 o;
            o.x = r[j + 0] + bias[n + 0];
            o.y = r[j + 1] + bias[n + 1];
            o.z = r[j + 2] + bias[n + 2];
            o.w = r[j + 3] + bias[n + 3];
            if (MODE == 0) {
                o.x = fmaxf(o.x, 0.f); o.y = fmaxf(o.y, 0.f);
                o.z = fmaxf(o.z, 0.f); o.w = fmaxf(o.w, 0.f);
            }
            if (MODE == 1) {
                const float* e = embed + (size_t)seqs[ty * 8 + i] * Hz + n;
                o.x += e[0]; o.y += e[1]; o.z += e[2]; o.w += e[3];
            }
            *(float4*)(Cp + (size_t)m * N + n) = o;
        }
    }
}

// ---------------- LayerNorm: g_x -> g_h (one warp per row) -------------------
__global__ __launch_bounds__(256)
void ln_k(const float* __restrict__ gam, const float* __restrict__ bet)
{
    int row  = blockIdx.x * 8 + (threadIdx.x >> 5);
    int lane = threadIdx.x & 31;
    const float* x = g_x + (size_t)row * Hz;

    float4 v[4];
    float sum = 0.f, sq = 0.f;
    #pragma unroll
    for (int i = 0; i < 4; i++) {
        v[i] = *(const float4*)(x + lane * 4 + i * 128);
        sum += v[i].x + v[i].y + v[i].z + v[i].w;
        sq  += v[i].x * v[i].x + v[i].y * v[i].y + v[i].z * v[i].z + v[i].w * v[i].w;
    }
    #pragma unroll
    for (int off = 16; off > 0; off >>= 1) {
        sum += __shfl_xor_sync(0xffffffffu, sum, off);
        sq  += __shfl_xor_sync(0xffffffffu, sq,  off);
    }
    float mean = sum * (1.f / 512.f);
    float var  = sq  * (1.f / 512.f) - mean * mean;
    float rs   = rsqrtf(var + 1e-5f);

    float* o = g_h + (size_t)row * Hz;
    #pragma unroll
    for (int i = 0; i < 4; i++) {
        int col = lane * 4 + i * 128;
        float4 gg = *(const float4*)(gam + col);
        float4 bb = *(const float4*)(bet + col);
        float4 r;
        r.x = (v[i].x - mean) * rs * gg.x + bb.x;
        r.y = (v[i].y - mean) * rs * gg.y + bb.y;
        r.z = (v[i].z - mean) * rs * gg.z + bb.z;
        r.w = (v[i].w - mean) * rs * gg.w + bb.w;
        *(float4*)(o + col) = r;
    }
}

// ---------------- 1/(k.k + 1e-6): one warp per row ---------------------------
__global__ __launch_bounds__(256)
void sinv_k()
{
    int idx  = blockIdx.x * 8 + (threadIdx.x >> 5);   // 0 .. 2*Mz-1
    int lane = threadIdx.x & 31;
    const float* kp = (idx < Mz) ? (g_ks + (size_t)idx * HALFz)
                                 : (g_ke + (size_t)(idx - Mz) * HALFz);
    float s = 0.f;
    #pragma unroll
    for (int i = 0; i < 2; i++) {
        float4 v = *(const float4*)(kp + lane * 4 + i * 128);
        s += v.x * v.x + v.y * v.y + v.z * v.z + v.w * v.w;
    }
    #pragma unroll
    for (int off = 16; off > 0; off >>= 1)
        s += __shfl_xor_sync(0xffffffffu, s, off);
    if (lane == 0) g_sinv[idx] = 1.f / (s + 1e-6f);
}

// ---------------- delta-rule scan (FFMA2 + prefetch ping-pong) ---------------
// grid (8 rowblocks, 2 matrices, 64 batches), 256 threads.
// warp handles 4 rows; 8 lanes per row, 16 f32x2 M-pairs per lane (registers).
struct ScanCtx {
    const float* kbase;
    const float* sv;
    int cb, row, mat;
};

// One delta step using k_t in Kc; prefetches k_{t+1} into Kn.
__device__ __forceinline__ void scan_step(int t, ull* M2, ull* Kc, ull* Kn,
                                          float &krow, float &inv,
                                          const ScanCtx &cx)
{
    // partial dot: M-row chunk . k chunk (pairs)
    ull a[4] = {0ull, 0ull, 0ull, 0ull};
    #pragma unroll
    for (int j = 0; j < 16; j++) fma2(a[j & 3], M2[j], Kc[j]);

    // prefetch k_{t+1} (overlaps the reduction below)
    const float* ktn = cx.kbase + (size_t)(t + 1) * HALFz;
    #pragma unroll
    for (int q = 0; q < 8; q++) {
        float4 v = __ldg((const float4*)(ktn + cx.cb + q * 4));
        Kn[2 * q]     = pk(v.x, v.y);
        Kn[2 * q + 1] = pk(v.z, v.w);
    }
    float krow_n = __ldg(ktn + cx.row);
    float inv_n  = __ldg(cx.sv + t + 1);

    // reduce partial dot across the 8 lanes of this row
    float2 s0 = upk(a[0]), s1 = upk(a[1]), s2 = upk(a[2]), s3 = upk(a[3]);
    float dot = (s0.x + s0.y) + (s1.x + s1.y) + (s2.x + s2.y) + (s3.x + s3.y);
    dot += __shfl_xor_sync(0xffffffffu, dot, 1, 8);
    dot += __shfl_xor_sync(0xffffffffu, dot, 2, 8);
    dot += __shfl_xor_sync(0xffffffffu, dot, 4, 8);

    float d = krow - dot * inv;
    if (cx.mat == 1) d *= (float)(t + 1) * (1.f / 1024.f);

    ull d2 = pk(d, d);
    #pragma unroll
    for (int j = 0; j < 16; j++) fma2(M2[j], d2, Kc[j]);

    krow = krow_n;
    inv  = inv_n;
}

__global__ __launch_bounds__(256, 2)
void scan_k()
{
    const int b   = blockIdx.z;
    const int mat = blockIdx.y;
    const int rb  = blockIdx.x;

    ScanCtx cx;
    cx.kbase = (mat == 0 ? g_ks : g_ke) + (size_t)b * Lz * HALFz;
    cx.sv    = g_sinv + mat * Mz + b * Lz;
    cx.mat   = mat;

    const int warp = threadIdx.x >> 5;
    const int lane = threadIdx.x & 31;
    const int sub  = lane >> 3;
    const int c    = lane & 7;
    cx.row = rb * 32 + warp * 4 + sub;
    cx.cb  = c * 32;

    ull M2[16];
    #pragma unroll
    for (int i = 0; i < 16; i++) M2[i] = 0ull;

    ull KA[16], KB[16];
    #pragma unroll
    for (int q = 0; q < 8; q++) {
        float4 v = __ldg((const float4*)(cx.kbase + cx.cb + q * 4));
        KA[2 * q]     = pk(v.x, v.y);
        KA[2 * q + 1] = pk(v.z, v.w);
    }
    float krow = __ldg(cx.kbase + cx.row);
    float inv  = __ldg(cx.sv);

    // 1023 delta steps: 511 ping-pong pairs + 1 tail step.
    for (int t = 0; t < Lz - 2; t += 2) {
        scan_step(t,     M2, KA, KB, krow, inv, cx);
        scan_step(t + 1, M2, KB, KA, krow, inv, cx);
    }
    scan_step(Lz - 2, M2, KA, KB, krow, inv, cx);   // prefetches k_{L-1} into KB

    // final query: c = M . k_{L-1}
    ull a[4] = {0ull, 0ull, 0ull, 0ull};
    #pragma unroll
    for (int j = 0; j < 16; j++) fma2(a[j & 3], M2[j], KB[j]);
    float2 s0 = upk(a[0]), s1 = upk(a[1]), s2 = upk(a[2]), s3 = upk(a[3]);
    float dot = (s0.x + s0.y) + (s1.x + s1.y) + (s2.x + s2.y) + (s3.x + s3.y);
    dot += __shfl_xor_sync(0xffffffffu, dot, 1, 8);
    dot += __shfl_xor_sync(0xffffffffu, dot, 2, 8);
    dot += __shfl_xor_sync(0xffffffffu, dot, 4, 8);
    if (c == 0) g_c[b * (2 * HALFz) + mat * HALFz + cx.row] = dot;
}

// ---------------- logits: out = c @ out_w + out_b ---------------------------
__global__ __launch_bounds__(256)
void out_k(const float* __restrict__ W, const float* __restrict__ ob,
           float* __restrict__ out)
{
    __shared__ float sc[512][16];      // k-major so float4 over m works
    const int mt  = blockIdx.y;
    const int tid = threadIdx.x;

    for (int i = tid; i < 16 * 512; i += 256) {
        int mm = i >> 9, k = i & 511;
        sc[k][mm] = g_c[(mt * 16 + mm) * 512 + k];
    }
    __syncthreads();

    const int n = blockIdx.x * 256 + tid;
    float acc[16];
    #pragma unroll
    for (int m = 0; m < 16; m++) acc[m] = 0.f;

    #pragma unroll 8
    for (int k = 0; k < 512; k++) {
        float w = __ldg(W + (size_t)k * Vz + n);
        #pragma unroll
        for (int q = 0; q < 4; q++) {
            float4 s = *(const float4*)&sc[k][q * 4];
            acc[q * 4 + 0] += s.x * w;
            acc[q * 4 + 1] += s.y * w;
            acc[q * 4 + 2] += s.z * w;
            acc[q * 4 + 3] += s.w * w;
        }
    }
    float bb = ob[n];
    #pragma unroll
    for (int m = 0; m < 16; m++)
        out[(size_t)(mt * 16 + m) * Vz + n] = acc[m] + bb;
}

// ---------------- launch ------------------------------------------------------
extern "C" void kernel_launch(void* const* d_in, const int* in_sizes, int n_in,
                              void* d_out, int out_size)
{
    (void)in_sizes; (void)n_in; (void)out_size;
    const int*   seq    = (const int*)  d_in[0];
    const float* embed  = (const float*)d_in[1];
    const float* ff_w1  = (const float*)d_in[2];
    const float* ff_b1  = (const float*)d_in[3];
    const float* ff_w2  = (const float*)d_in[4];
    const float* ff_b2  = (const float*)d_in[5];
    const float* ln_g   = (const float*)d_in[6];
    const float* ln_b   = (const float*)d_in[7];
    const float* sem_w  = (const float*)d_in[8];
    const float* sem_b  = (const float*)d_in[9];
    const float* epi_w  = (const float*)d_in[10];
    const float* epi_b  = (const float*)d_in[11];
    const float* out_w  = (const float*)d_in[12];
    const float* out_b  = (const float*)d_in[13];
    float* out = (float*)d_out;

    gemm_k<0><<<dim3(8, 512), 256>>>(seq, embed, ff_w1, ff_b1, Mz, 1024, 512, 0);
    gemm_k<1><<<dim3(4, 512), 256>>>(seq, embed, ff_w2, ff_b2, Mz, 512, 1024, 0);
    ln_k<<<Mz / 8, 256>>>(ln_g, ln_b);
    gemm_k<2><<<dim3(2, 512), 256>>>(seq, embed, sem_w, sem_b, Mz, 256, 512, 0);
    gemm_k<2><<<dim3(2, 512), 256>>>(seq, embed, epi_w, epi_b, Mz, 256, 512, 1);
    sinv_k<<<(2 * Mz) / 8, 256>>>();
    scan_k<<<dim3(8, 2, 64), 256>>>();
    out_k<<<dim3(125, 4), 256>>>(out_w, out_b, out);
}

// round 4
// speedup vs baseline: 1.7296x; 1.6190x over previous
#include <cuda_runtime.h>
#include <cstdint>

#define Bz   64
#define Lz   1024
#define Hz   512
#define HALFz 256
#define Vz   32000
#define Mz   (Bz*Lz)          /* 65536 rows */
#define NCH  16               /* chunks of 64 steps */

typedef unsigned long long ull;

// ---------------- f32x2 packed-math helpers (sm_103a FFMA2) ------------------
__device__ __forceinline__ void fma2(ull &d, ull a, ull b) {
    asm("fma.rn.f32x2 %0, %1, %2, %0;" : "+l"(d) : "l"(a), "l"(b));
}
__device__ __forceinline__ ull pk(float lo, float hi) {
    ull r; asm("mov.b64 %0, {%1, %2};" : "=l"(r) : "f"(lo), "f"(hi)); return r;
}
__device__ __forceinline__ float2 upk(ull v) {
    float2 r; asm("mov.b64 {%0, %1}, %2;" : "=f"(r.x), "=f"(r.y) : "l"(v)); return r;
}

// ---------------- scratch (device globals; no allocations allowed) ----------
__device__ float g_relu[(size_t)Mz * 1024];   // 256 MB
__device__ float g_x   [(size_t)Mz * Hz];     // 128 MB
__device__ float g_h   [(size_t)Mz * Hz];     // 128 MB
__device__ float g_ks  [(size_t)Mz * HALFz];  // 64 MB
__device__ float g_ke  [(size_t)Mz * HALFz];  // 64 MB
__device__ float g_sinv[2 * Mz];              // beta = 1/(k.k+eps)
__device__ float g_gram[(size_t)2 * Bz * NCH * 64 * 64];  // 33.5 MB Gram per chunk
__device__ float g_c   [Bz * 2 * HALFz];      // concat(cs, ce)

// ---------------- tiled FP32 GEMM (FFMA2 inner product) ----------------------
template<int MODE>
__global__ __launch_bounds__(256)
void gemm_k(const int* __restrict__ seq, const float* __restrict__ embed,
            const float* __restrict__ Bm, const float* __restrict__ bias,
            int M, int N, int K, int outsel)
{
    constexpr int BM = 128, BN = 128, BK = 16;
    __shared__ float As[BK][BM];
    __shared__ float Bs[BK][BN];
    __shared__ int   seqs[BM];

    const int tid = threadIdx.x;
    const int m0 = blockIdx.y * BM;
    const int n0 = blockIdx.x * BN;

    if (MODE != 2) { if (tid < BM) seqs[tid] = seq[m0 + tid]; }

    const int am = tid >> 2;
    const int ak = (tid & 3) << 2;
    const int bk = tid >> 5;
    const int bn = (tid & 31) << 2;
    const int ty = tid >> 4;
    const int tx = tid & 15;

    const float* Ap;
    float* Cp;
    if (MODE == 0)      { Ap = nullptr; Cp = g_relu; }
    else if (MODE == 1) { Ap = g_relu;  Cp = g_x; }
    else                { Ap = g_h;     Cp = outsel ? g_ke : g_ks; }

    ull acc2[8][4];
    #pragma unroll
    for (int i = 0; i < 8; i++)
        #pragma unroll
        for (int j = 0; j < 4; j++) acc2[i][j] = 0ull;

    __syncthreads();

    for (int k0 = 0; k0 < K; k0 += BK) {
        #pragma unroll
        for (int p = 0; p < 2; p++) {
            int m = am + p * 64;
            const float* src;
            if (MODE == 0) src = embed + (size_t)seqs[m] * Hz + k0 + ak;
            else           src = Ap + (size_t)(m0 + m) * K + k0 + ak;
            float4 v = *(const float4*)src;
            As[ak + 0][m] = v.x; As[ak + 1][m] = v.y;
            As[ak + 2][m] = v.z; As[ak + 3][m] = v.w;
        }
        #pragma unroll
        for (int p = 0; p < 2; p++) {
            int kk = bk + p * 8;
            float4 v = *(const float4*)(Bm + (size_t)(k0 + kk) * N + n0 + bn);
            *(float4*)&Bs[kk][bn] = v;
        }
        __syncthreads();

        #pragma unroll
        for (int kk = 0; kk < BK; kk++) {
            float ra[8];
            ull rb2[4];
            *(float4*)(ra)     = *(const float4*)&As[kk][ty * 8];
            *(float4*)(ra + 4) = *(const float4*)&As[kk][ty * 8 + 4];
            #pragma unroll
            for (int j = 0; j < 4; j++)
                rb2[j] = *(const ull*)&Bs[kk][tx * 8 + 2 * j];
            #pragma unroll
            for (int i = 0; i < 8; i++) {
                ull ra2 = pk(ra[i], ra[i]);
                #pragma unroll
                for (int j = 0; j < 4; j++) fma2(acc2[i][j], ra2, rb2[j]);
            }
        }
        __syncthreads();
    }

    #pragma unroll
    for (int i = 0; i < 8; i++) {
        int m = m0 + ty * 8 + i;
        float r[8];
        #pragma unroll
        for (int j = 0; j < 4; j++) {
            float2 t = upk(acc2[i][j]);
            r[2 * j] = t.x; r[2 * j + 1] = t.y;
        }
        #pragma unroll
        for (int j = 0; j < 8; j += 4) {
            int n = n0 + tx * 8 + j;
            float4 o;
            o.x = r[j + 0] + bias[n + 0];
            o.y = r[j + 1] + bias[n + 1];
            o.z = r[j + 2] + bias[n + 2];
            o.w = r[j + 3] + bias[n + 3];
            if (MODE == 0) {
                o.x = fmaxf(o.x, 0.f); o.y = fmaxf(o.y, 0.f);
                o.z = fmaxf(o.z, 0.f); o.w = fmaxf(o.w, 0.f);
            }
            if (MODE == 1) {
                const float* e = embed + (size_t)seqs[ty * 8 + i] * Hz + n;
                o.x += e[0]; o.y += e[1]; o.z += e[2]; o.w += e[3];
            }
            *(float4*)(Cp + (size_t)m * N + n) = o;
        }
    }
}

// ---------------- LayerNorm: g_x -> g_h --------------------------------------
__global__ __launch_bounds__(256)
void ln_k(const float* __restrict__ gam, const float* __restrict__ bet)
{
    int row  = blockIdx.x * 8 + (threadIdx.x >> 5);
    int lane = threadIdx.x & 31;
    const float* x = g_x + (size_t)row * Hz;

    float4 v[4];
    float sum = 0.f, sq = 0.f;
    #pragma unroll
    for (int i = 0; i < 4; i++) {
        v[i] = *(const float4*)(x + lane * 4 + i * 128);
        sum += v[i].x + v[i].y + v[i].z + v[i].w;
        sq  += v[i].x * v[i].x + v[i].y * v[i].y + v[i].z * v[i].z + v[i].w * v[i].w;
    }
    #pragma unroll
    for (int off = 16; off > 0; off >>= 1) {
        sum += __shfl_xor_sync(0xffffffffu, sum, off);
        sq  += __shfl_xor_sync(0xffffffffu, sq,  off);
    }
    float mean = sum * (1.f / 512.f);
    float var  = sq  * (1.f / 512.f) - mean * mean;
    float rs   = rsqrtf(var + 1e-5f);

    float* o = g_h + (size_t)row * Hz;
    #pragma unroll
    for (int i = 0; i < 4; i++) {
        int col = lane * 4 + i * 128;
        float4 gg = *(const float4*)(gam + col);
        float4 bb = *(const float4*)(bet + col);
        float4 r;
        r.x = (v[i].x - mean) * rs * gg.x + bb.x;
        r.y = (v[i].y - mean) * rs * gg.y + bb.y;
        r.z = (v[i].z - mean) * rs * gg.z + bb.z;
        r.w = (v[i].w - mean) * rs * gg.w + bb.w;
        *(float4*)(o + col) = r;
    }
}

// ---------------- beta = 1/(k.k + 1e-6) --------------------------------------
__global__ __launch_bounds__(256)
void sinv_k()
{
    int idx  = blockIdx.x * 8 + (threadIdx.x >> 5);
    int lane = threadIdx.x & 31;
    const float* kp = (idx < Mz) ? (g_ks + (size_t)idx * HALFz)
                                 : (g_ke + (size_t)(idx - Mz) * HALFz);
    float s = 0.f;
    #pragma unroll
    for (int i = 0; i < 2; i++) {
        float4 v = *(const float4*)(kp + lane * 4 + i * 128);
        s += v.x * v.x + v.y * v.y + v.z * v.z + v.w * v.w;
    }
    #pragma unroll
    for (int off = 16; off > 0; off >>= 1)
        s += __shfl_xor_sync(0xffffffffu, s, off);
    if (lane == 0) g_sinv[idx] = 1.f / (s + 1e-6f);
}

// ---------------- per-chunk Gram matrices A[t][s] = k_t . k_s ----------------
// grid (NCH, 2, Bz), 256 threads. Each block: 64x64 Gram of one chunk.
__global__ __launch_bounds__(256)
void gram_k()
{
    __shared__ float Kh[64 * 129];
    const int ch = blockIdx.x, mat = blockIdx.y, b = blockIdx.z;
    const float* kbase = (mat ? g_ke : g_ks)
                         + (size_t)b * Lz * HALFz + (size_t)ch * 64 * HALFz;
    const int tid = threadIdx.x;
    const int t0 = (tid >> 4) * 4;     // 0..60
    const int s0 = (tid & 15) * 4;     // 0..60

    float acc[4][4];
    #pragma unroll
    for (int i = 0; i < 4; i++)
        #pragma unroll
        for (int q = 0; q < 4; q++) acc[i][q] = 0.f;

    const int row = tid >> 2;
    const int cb  = (tid & 3) * 32;

    for (int half = 0; half < 2; half++) {
        __syncthreads();
        #pragma unroll
        for (int d = 0; d < 8; d++) {
            float4 v = *(const float4*)(kbase + (size_t)row * HALFz + half * 128 + cb + 4 * d);
            float* w = Kh + row * 129 + cb + 4 * d;
            w[0] = v.x; w[1] = v.y; w[2] = v.z; w[3] = v.w;
        }
        __syncthreads();
        #pragma unroll 4
        for (int j = 0; j < 128; j++) {
            float a0 = Kh[(t0 + 0) * 129 + j], a1 = Kh[(t0 + 1) * 129 + j];
            float a2 = Kh[(t0 + 2) * 129 + j], a3 = Kh[(t0 + 3) * 129 + j];
            float b0 = Kh[(s0 + 0) * 129 + j], b1 = Kh[(s0 + 1) * 129 + j];
            float b2 = Kh[(s0 + 2) * 129 + j], b3 = Kh[(s0 + 3) * 129 + j];
            acc[0][0] += a0 * b0; acc[0][1] += a0 * b1; acc[0][2] += a0 * b2; acc[0][3] += a0 * b3;
            acc[1][0] += a1 * b0; acc[1][1] += a1 * b1; acc[1][2] += a1 * b2; acc[1][3] += a1 * b3;
            acc[2][0] += a2 * b0; acc[2][1] += a2 * b1; acc[2][2] += a2 * b2; acc[2][3] += a2 * b3;
            acc[3][0] += a3 * b0; acc[3][1] += a3 * b1; acc[3][2] += a3 * b2; acc[3][3] += a3 * b3;
        }
    }
    float* out = g_gram + ((size_t)(mat * Bz + b) * NCH + ch) * 4096;
    #pragma unroll
    for (int i = 0; i < 4; i++)
        #pragma unroll
        for (int q = 0; q < 4; q++)
            out[(t0 + i) * 64 + s0 + q] = acc[i][q];
}

// ---------------- chunked delta-rule scan ------------------------------------
// grid (4 rowblocks, 2 mats, 64 batches), 256 threads.
// Thread (r = tid&63, g = tid>>6) owns M[r0+r][g*64 .. g*64+63] in registers.
// Per 64-step chunk:  q = M0 K^T (GEMM) -> forward substitution (row-parallel,
// scalar chains, no shuffles) -> M += U^T K (GEMM).
__global__ __launch_bounds__(256)
void scan_k()
{
    extern __shared__ float sm[];
    float* Ks = sm;                       // [64][256]   16384 floats
    float* Qp = Ks + 64 * 256;            // [4][64*64]  16384
    float* As = Qp + 4 * 4096;            // [64*64]      4096
    float* Us = As + 4096;                // [64][64]     4096  (Us[t*64+r])
    float* Bs = Us + 4096;                // [64]         beta chunk

    const int tid = threadIdx.x;
    const int rb  = blockIdx.x;           // 0..3
    const int mat = blockIdx.y;
    const int b   = blockIdx.z;
    const int r   = tid & 63;
    const int g   = tid >> 6;
    const int r0  = rb * 64;

    const float* kbase = (mat ? g_ke : g_ks) + (size_t)b * Lz * HALFz;
    const float* sv    = g_sinv + mat * Mz + b * Lz;
    const float* gbase = g_gram + (size_t)(mat * Bz + b) * NCH * 4096;

    ull M2[32];
    #pragma unroll
    for (int i = 0; i < 32; i++) M2[i] = 0ull;

    for (int ch = 0; ch < NCH; ch++) {
        const int c0   = ch * 64;
        const int clen = (ch == NCH - 1) ? 63 : 64;

        __syncthreads();   // previous chunk finished with Ks/Us
        // load K chunk (16384 floats, coalesced float4)
        #pragma unroll
        for (int q = 0; q < 16; q++) {
            int off = tid * 4 + q * 1024;
            *(float4*)(Ks + off) = *(const float4*)(kbase + (size_t)c0 * HALFz + off);
        }
        // load Gram chunk
        #pragma unroll
        for (int q = 0; q < 4; q++) {
            int off = tid * 4 + q * 1024;
            *(float4*)(As + off) = *(const float4*)(gbase + ch * 4096 + off);
        }
        if (tid < 64) Bs[tid] = sv[c0 + tid];
        __syncthreads();

        // ---- q phase: q0[t][r] partial over this thread's 64 columns
        #pragma unroll 1
        for (int t = 0; t < 64; t++) {
            ull a0 = 0ull, a1 = 0ull;
            const ull* kt2 = (const ull*)(Ks + t * 256 + g * 64);
            #pragma unroll
            for (int jj = 0; jj < 32; jj += 2) {
                fma2(a0, M2[jj],     kt2[jj]);
                fma2(a1, M2[jj + 1], kt2[jj + 1]);
            }
            float2 s0 = upk(a0), s1 = upk(a1);
            Qp[g * 4096 + t * 64 + r] = (s0.x + s0.y) + (s1.x + s1.y);
        }
        __syncthreads();
        // reduce partials across the 4 column groups
        #pragma unroll
        for (int e = 0; e < 16; e++) {
            int idx = tid + e * 256;
            Qp[idx] = Qp[idx] + Qp[idx + 4096] + Qp[idx + 2 * 4096] + Qp[idx + 3 * 4096];
        }
        __syncthreads();

        // ---- forward substitution (threads 0..63; each owns one M-row)
        if (g == 0) {
            for (int t = 0; t < clen; t++) {
                float s0 = 0.f, s1 = 0.f, s2 = 0.f, s3 = 0.f;
                const float* At = As + t * 64;
                int s = 0;
                for (; s + 4 <= t; s += 4) {
                    s0 += At[s + 0] * Us[(s + 0) * 64 + r];
                    s1 += At[s + 1] * Us[(s + 1) * 64 + r];
                    s2 += At[s + 2] * Us[(s + 2) * 64 + r];
                    s3 += At[s + 3] * Us[(s + 3) * 64 + r];
                }
                for (; s < t; s++) s0 += At[s] * Us[s * 64 + r];
                float S = (s0 + s1) + (s2 + s3);
                float alpha = (mat == 0) ? 1.f : (float)(c0 + t + 1) * (1.f / 1024.f);
                float gam = alpha * Bs[t];
                Us[t * 64 + r] = alpha * Ks[t * 256 + r0 + r]
                               - gam * (Qp[t * 64 + r] + S);
            }
        }
        __syncthreads();

        // ---- update: M += U^T K
        #pragma unroll 1
        for (int t = 0; t < clen; t++) {
            float u = Us[t * 64 + r];
            ull u2 = pk(u, u);
            const ull* kt2 = (const ull*)(Ks + t * 256 + g * 64);
            #pragma unroll
            for (int jj = 0; jj < 32; jj++) fma2(M2[jj], u2, kt2[jj]);
        }
    }

    // ---- final query: c = M . k_{L-1} (row 63 of last chunk, still in Ks)
    {
        ull a0 = 0ull, a1 = 0ull;
        const ull* kt2 = (const ull*)(Ks + 63 * 256 + g * 64);
        #pragma unroll
        for (int jj = 0; jj < 32; jj += 2) {
            fma2(a0, M2[jj],     kt2[jj]);
            fma2(a1, M2[jj + 1], kt2[jj + 1]);
        }
        float2 s0 = upk(a0), s1 = upk(a1);
        Qp[g * 4096 + r] = (s0.x + s0.y) + (s1.x + s1.y);
    }
    __syncthreads();
    if (g == 0)
        g_c[b * (2 * HALFz) + mat * HALFz + r0 + r] =
            Qp[r] + Qp[4096 + r] + Qp[2 * 4096 + r] + Qp[3 * 4096 + r];
}

// ---------------- logits: out = c @ out_w + out_b ----------------------------
__global__ __launch_bounds__(256)
void out_k(const float* __restrict__ W, const float* __restrict__ ob,
           float* __restrict__ out)
{
    __shared__ float sc[512][16];
    const int mt  = blockIdx.y;
    const int tid = threadIdx.x;

    for (int i = tid; i < 16 * 512; i += 256) {
        int mm = i >> 9, k = i & 511;
        sc[k][mm] = g_c[(mt * 16 + mm) * 512 + k];
    }
    __syncthreads();

    const int n = blockIdx.x * 256 + tid;
    float acc[16];
    #pragma unroll
    for (int m = 0; m < 16; m++) acc[m] = 0.f;

    #pragma unroll 8
    for (int k = 0; k < 512; k++) {
        float w = __ldg(W + (size_t)k * Vz + n);
        #pragma unroll
        for (int q = 0; q < 4; q++) {
            float4 s = *(const float4*)&sc[k][q * 4];
            acc[q * 4 + 0] += s.x * w;
            acc[q * 4 + 1] += s.y * w;
            acc[q * 4 + 2] += s.z * w;
            acc[q * 4 + 3] += s.w * w;
        }
    }
    float bb = ob[n];
    #pragma unroll
    for (int m = 0; m < 16; m++)
        out[(size_t)(mt * 16 + m) * Vz + n] = acc[m] + bb;
}

// ---------------- launch ------------------------------------------------------
extern "C" void kernel_launch(void* const* d_in, const int* in_sizes, int n_in,
                              void* d_out, int out_size)
{
    (void)in_sizes; (void)n_in; (void)out_size;
    const int*   seq    = (const int*)  d_in[0];
    const float* embed  = (const float*)d_in[1];
    const float* ff_w1  = (const float*)d_in[2];
    const float* ff_b1  = (const float*)d_in[3];
    const float* ff_w2  = (const float*)d_in[4];
    const float* ff_b2  = (const float*)d_in[5];
    const float* ln_g   = (const float*)d_in[6];
    const float* ln_b   = (const float*)d_in[7];
    const float* sem_w  = (const float*)d_in[8];
    const float* sem_b  = (const float*)d_in[9];
    const float* epi_w  = (const float*)d_in[10];
    const float* epi_b  = (const float*)d_in[11];
    const float* out_w  = (const float*)d_in[12];
    const float* out_b  = (const float*)d_in[13];
    float* out = (float*)d_out;

    static int smem_set = 0;
    const int scan_smem = (16384 + 16384 + 4096 + 4096 + 64) * 4;  // 164096 B
    if (!smem_set) {
        cudaFuncSetAttribute(scan_k, cudaFuncAttributeMaxDynamicSharedMemorySize,
                             scan_smem);
        smem_set = 1;
    }

    gemm_k<0><<<dim3(8, 512), 256>>>(seq, embed, ff_w1, ff_b1, Mz, 1024, 512, 0);
    gemm_k<1><<<dim3(4, 512), 256>>>(seq, embed, ff_w2, ff_b2, Mz, 512, 1024, 0);
    ln_k<<<Mz / 8, 256>>>(ln_g, ln_b);
    gemm_k<2><<<dim3(2, 512), 256>>>(seq, embed, sem_w, sem_b, Mz, 256, 512, 0);
    gemm_k<2><<<dim3(2, 512), 256>>>(seq, embed, epi_w, epi_b, Mz, 256, 512, 1);
    sinv_k<<<(2 * Mz) / 8, 256>>>();
    gram_k<<<dim3(NCH, 2, Bz), 256>>>();
    scan_k<<<dim3(4, 2, Bz), 256, scan_smem>>>();
    out_k<<<dim3(125, 4), 256>>>(out_w, out_b, out);
}

// round 9
// speedup vs baseline: 3.2081x; 1.8548x over previous
#include <cuda_runtime.h>
#include <cuda_bf16.h>
#include <cstdint>

#define Bz   64
#define Lz   1024
#define Hz   512
#define HALFz 256
#define Vz   32000
#define Mz   (Bz*Lz)          /* 65536 rows */
#define NCH  16               /* chunks of 64 steps */

typedef unsigned long long ull;

// ---------------- f32x2 packed-math helpers ----------------------------------
__device__ __forceinline__ void fma2(ull &d, ull a, ull b) {
    asm("fma.rn.f32x2 %0, %1, %2, %0;" : "+l"(d) : "l"(a), "l"(b));
}
__device__ __forceinline__ ull pk(float lo, float hi) {
    ull r; asm("mov.b64 %0, {%1, %2};" : "=l"(r) : "f"(lo), "f"(hi)); return r;
}
__device__ __forceinline__ float2 upk(ull v) {
    float2 r; asm("mov.b64 {%0, %1}, %2;" : "=f"(r.x), "=f"(r.y) : "l"(v)); return r;
}

// ---------------- warp-mma helpers (arch-portable HMMA) ----------------------
__device__ __forceinline__ uint32_t smem_u32(const void* p) {
    uint32_t a;
    asm("{ .reg .u64 t; cvta.to.shared.u64 t, %1; cvt.u32.u64 %0, t; }"
        : "=r"(a) : "l"(p));
    return a;
}
__device__ __forceinline__ void ldm4(uint32_t* r, uint32_t addr) {
    asm volatile("ldmatrix.sync.aligned.m8n8.x4.shared.b16 {%0,%1,%2,%3}, [%4];"
        : "=r"(r[0]), "=r"(r[1]), "=r"(r[2]), "=r"(r[3]) : "r"(addr));
}
__device__ __forceinline__ void mma_bf16(float* c, const uint32_t* a,
                                         const uint32_t* b) {
    asm volatile("mma.sync.aligned.m16n8k16.row.col.f32.bf16.bf16.f32 "
        "{%0,%1,%2,%3}, {%4,%5,%6,%7}, {%8,%9}, {%0,%1,%2,%3};"
        : "+f"(c[0]), "+f"(c[1]), "+f"(c[2]), "+f"(c[3])
        : "r"(a[0]), "r"(a[1]), "r"(a[2]), "r"(a[3]), "r"(b[0]), "r"(b[1]));
}

// ---------------- scratch ----------------------------------------------------
__device__ float g_relu[(size_t)Mz * 1024];
__device__ float g_x   [(size_t)Mz * Hz];
__device__ float g_h   [(size_t)Mz * Hz];
__device__ float g_ks  [(size_t)Mz * HALFz];
__device__ float g_ke  [(size_t)Mz * HALFz];
__device__ float g_sinv[2 * Mz];
__device__ float g_gram[(size_t)2 * Bz * NCH * 64 * 64];
__device__ float g_c   [Bz * 2 * HALFz];
__device__ __nv_bfloat16 g_w1hi[1024 * 512], g_w1lo[1024 * 512];
__device__ __nv_bfloat16 g_w2hi[512 * 1024], g_w2lo[512 * 1024];
__device__ __nv_bfloat16 g_swhi[256 * 512],  g_swlo[256 * 512];
__device__ __nv_bfloat16 g_ewhi[256 * 512],  g_ewlo[256 * 512];

// ---------------- weight transpose + bf16 split:  W[K][N] -> [N][K] hi/lo ----
__global__ __launch_bounds__(256)
void wsplit_k(const float* __restrict__ W, __nv_bfloat16* __restrict__ hi,
              __nv_bfloat16* __restrict__ lo, int K, int N)
{
    __shared__ float t[32][33];
    const int n0 = blockIdx.x * 32, k0 = blockIdx.y * 32;
    const int tx = threadIdx.x & 31, ty = threadIdx.x >> 5;
    #pragma unroll
    for (int p = 0; p < 4; p++) {
        int kk = ty + p * 8;
        t[kk][tx] = W[(size_t)(k0 + kk) * N + n0 + tx];
    }
    __syncthreads();
    #pragma unroll
    for (int p = 0; p < 4; p++) {
        int r = ty + p * 8;
        float v = t[tx][r];
        __nv_bfloat16 h = __float2bfloat16(v);
        __nv_bfloat16 l = __float2bfloat16(v - __bfloat162float(h));
        size_t o = (size_t)(n0 + r) * K + k0 + tx;
        hi[o] = h; lo[o] = l;
    }
}

// ---------------- HMMA split-bf16 GEMM ---------------------------------------
// 128x128 block, BK=32, 8 warps (4m x 2n), warp tile 32x64, m16n8k16.
// MODE 0: A = embed[seq[m]] fp32 (split inline), epi relu(d+bias)
// MODE 1: A = Afp,                               epi d+bias+embed[seq[m]][n]
// MODE 2: A = Afp,                               epi d+bias
#define MG_STR  40                       /* bf16 per smem row (32 + 8 pad)   */
#define MG_AH   0
#define MG_AL   (128 * MG_STR)
#define MG_BH   (2 * 128 * MG_STR)
#define MG_BL   (3 * 128 * MG_STR)
#define MG_STAGE (4 * 128 * MG_STR)      /* bf16 units = 20480               */
#define MG_SMEM (2 * MG_STAGE * 2)       /* bytes = 81920                    */

template<int MODE>
__global__ __launch_bounds__(256, 2)
void mgemm_k(const int* __restrict__ seq, const float* __restrict__ embed,
             const float* __restrict__ Afp,
             const __nv_bfloat16* __restrict__ Bhi,
             const __nv_bfloat16* __restrict__ Blo,
             const float* __restrict__ bias, float* __restrict__ Cout,
             int Kfull, int Nfull)
{
    extern __shared__ __nv_bfloat16 smb[];
    __shared__ int seqs[128];

    const int tid  = threadIdx.x;
    const int lane = tid & 31;
    const int wid  = tid >> 5;
    const int wm   = wid & 3;            // 0..3: m-tile of 32 rows
    const int wn   = wid >> 2;           // 0..1: n-tile of 64 cols
    const int m0 = blockIdx.y * 128;
    const int n0 = blockIdx.x * 128;

    if (MODE != 2 && tid < 128) seqs[tid] = seq[m0 + tid];
    __syncthreads();

    float acc[2][8][4];
    #pragma unroll
    for (int i = 0; i < 2; i++)
        #pragma unroll
        for (int n = 0; n < 8; n++)
            #pragma unroll
            for (int q = 0; q < 4; q++) acc[i][n][q] = 0.f;

    const int nk = Kfull >> 5;           // BK = 32

    // stage loader
    auto mg_load = [&](int kc, int s) {
        __nv_bfloat16* sb = smb + s * MG_STAGE;
        const int k0 = kc << 5;
        {   // A: fp32 -> hi/lo
            const int row0 = tid >> 3;
            const int k4   = (tid & 7) << 2;
            #pragma unroll
            for (int p = 0; p < 4; p++) {
                int row = row0 + p * 32;
                const float* src;
                if (MODE == 0) src = embed + (size_t)seqs[row] * Hz + k0 + k4;
                else           src = Afp + (size_t)(m0 + row) * Kfull + k0 + k4;
                float4 v = *(const float4*)src;
                __nv_bfloat162 h01 = __floats2bfloat162_rn(v.x, v.y);
                __nv_bfloat162 h23 = __floats2bfloat162_rn(v.z, v.w);
                __nv_bfloat162 l01 = __floats2bfloat162_rn(
                    v.x - __bfloat162float(h01.x), v.y - __bfloat162float(h01.y));
                __nv_bfloat162 l23 = __floats2bfloat162_rn(
                    v.z - __bfloat162float(h23.x), v.w - __bfloat162float(h23.y));
                int o = row * MG_STR + k4;
                *(uint2*)(sb + MG_AH + o) = make_uint2(*(uint32_t*)&h01, *(uint32_t*)&h23);
                *(uint2*)(sb + MG_AL + o) = make_uint2(*(uint32_t*)&l01, *(uint32_t*)&l23);
            }
        }
        {   // B: pre-split bf16 [N][K]
            const int row0 = tid >> 2;
            const int k8   = (tid & 3) << 3;
            #pragma unroll
            for (int p = 0; p < 2; p++) {
                int n = row0 + p * 64;
                size_t o = (size_t)(n0 + n) * Kfull + k0 + k8;
                int d = n * MG_STR + k8;
                *(uint4*)(sb + MG_BH + d) = *(const uint4*)(Bhi + o);
                *(uint4*)(sb + MG_BL + d) = *(const uint4*)(Blo + o);
            }
        }
    };

    mg_load(0, 0);
    __syncthreads();

    for (int kc = 0; kc < nk; kc++) {
        if (kc + 1 < nk) mg_load(kc + 1, (kc + 1) & 1);

        const __nv_bfloat16* sb = smb + (kc & 1) * MG_STAGE;
        const uint32_t aH = smem_u32(sb + MG_AH);
        const uint32_t aL = smem_u32(sb + MG_AL);
        const uint32_t bH = smem_u32(sb + MG_BH);
        const uint32_t bL = smem_u32(sb + MG_BL);

        #pragma unroll
        for (int ks = 0; ks < 2; ks++) {
            // A fragments: rows = wm*32 + i*16 + (lane&15), col = ks*16 + (lane>>4)*8
            uint32_t ah[2][4], al[2][4];
            const int ar = wm * 32 + (lane & 15);
            const int ac = ks * 16 + ((lane >> 4) << 3);
            #pragma unroll
            for (int i = 0; i < 2; i++) {
                uint32_t off = ((ar + i * 16) * MG_STR + ac) * 2;
                ldm4(ah[i], aH + off);
                ldm4(al[i], aL + off);
            }
            #pragma unroll
            for (int j = 0; j < 4; j++) {
                // B x4: lanes0-7 n+0..7@k, 8-15 n+0..7@k+8, 16-23 n+8..15@k, 24-31 n+8..15@k+8
                const int nr = wn * 64 + j * 16 + (lane & 7) + ((lane >> 4) << 3);
                const int kc2 = ks * 16 + (((lane >> 3) & 1) << 3);
                uint32_t off = (nr * MG_STR + kc2) * 2;
                uint32_t bh[4], bl[4];
                ldm4(bh, bH + off);
                ldm4(bl, bL + off);
                #pragma unroll
                for (int i = 0; i < 2; i++) {
                    mma_bf16(acc[i][2 * j],     ah[i], bh);
                    mma_bf16(acc[i][2 * j + 1], ah[i], bh + 2);
                    mma_bf16(acc[i][2 * j],     ah[i], bl);
                    mma_bf16(acc[i][2 * j + 1], ah[i], bl + 2);
                    mma_bf16(acc[i][2 * j],     al[i], bh);
                    mma_bf16(acc[i][2 * j + 1], al[i], bh + 2);
                }
            }
        }
        __syncthreads();
    }

    // epilogue
    #pragma unroll
    for (int i = 0; i < 2; i++) {
        int rlo = wm * 32 + i * 16 + (lane >> 2);
        #pragma unroll
        for (int n = 0; n < 8; n++) {
            int col = n0 + wn * 64 + n * 8 + (lane & 3) * 2;
            float b0 = bias[col], b1 = bias[col + 1];
            #pragma unroll
            for (int h = 0; h < 2; h++) {
                int rr = rlo + h * 8;
                size_t m = m0 + rr;
                float2 o;
                o.x = acc[i][n][2 * h + 0] + b0;
                o.y = acc[i][n][2 * h + 1] + b1;
                if (MODE == 0) { o.x = fmaxf(o.x, 0.f); o.y = fmaxf(o.y, 0.f); }
                if (MODE == 1) {
                    const float* e = embed + (size_t)seqs[rr] * Hz + col;
                    o.x += e[0]; o.y += e[1];
                }
                *(float2*)(Cout + m * Nfull + col) = o;
            }
        }
    }
}

// ---------------- LayerNorm --------------------------------------------------
__global__ __launch_bounds__(256)
void ln_k(const float* __restrict__ gam, const float* __restrict__ bet)
{
    int row  = blockIdx.x * 8 + (threadIdx.x >> 5);
    int lane = threadIdx.x & 31;
    const float* x = g_x + (size_t)row * Hz;

    float4 v[4];
    float sum = 0.f, sq = 0.f;
    #pragma unroll
    for (int i = 0; i < 4; i++) {
        v[i] = *(const float4*)(x + lane * 4 + i * 128);
        sum += v[i].x + v[i].y + v[i].z + v[i].w;
        sq  += v[i].x * v[i].x + v[i].y * v[i].y + v[i].z * v[i].z + v[i].w * v[i].w;
    }
    #pragma unroll
    for (int off = 16; off > 0; off >>= 1) {
        sum += __shfl_xor_sync(0xffffffffu, sum, off);
        sq  += __shfl_xor_sync(0xffffffffu, sq,  off);
    }
    float mean = sum * (1.f / 512.f);
    float var  = sq  * (1.f / 512.f) - mean * mean;
    float rs   = rsqrtf(var + 1e-5f);

    float* o = g_h + (size_t)row * Hz;
    #pragma unroll
    for (int i = 0; i < 4; i++) {
        int col = lane * 4 + i * 128;
        float4 gg = *(const float4*)(gam + col);
        float4 bb = *(const float4*)(bet + col);
        float4 r;
        r.x = (v[i].x - mean) * rs * gg.x + bb.x;
        r.y = (v[i].y - mean) * rs * gg.y + bb.y;
        r.z = (v[i].z - mean) * rs * gg.z + bb.z;
        r.w = (v[i].w - mean) * rs * gg.w + bb.w;
        *(float4*)(o + col) = r;
    }
}

// ---------------- beta = 1/(k.k + 1e-6) --------------------------------------
__global__ __launch_bounds__(256)
void sinv_k()
{
    int idx  = blockIdx.x * 8 + (threadIdx.x >> 5);
    int lane = threadIdx.x & 31;
    const float* kp = (idx < Mz) ? (g_ks + (size_t)idx * HALFz)
                                 : (g_ke + (size_t)(idx - Mz) * HALFz);
    float s = 0.f;
    #pragma unroll
    for (int i = 0; i < 2; i++) {
        float4 v = *(const float4*)(kp + lane * 4 + i * 128);
        s += v.x * v.x + v.y * v.y + v.z * v.z + v.w * v.w;
    }
    #pragma unroll
    for (int off = 16; off > 0; off >>= 1)
        s += __shfl_xor_sync(0xffffffffu, s, off);
    if (lane == 0) g_sinv[idx] = 1.f / (s + 1e-6f);
}

// ---------------- per-chunk Gram ---------------------------------------------
__global__ __launch_bounds__(256)
void gram_k()
{
    __shared__ float Kh[64 * 129];
    const int ch = blockIdx.x, mat = blockIdx.y, b = blockIdx.z;
    const float* kbase = (mat ? g_ke : g_ks)
                         + (size_t)b * Lz * HALFz + (size_t)ch * 64 * HALFz;
    const int tid = threadIdx.x;
    const int t0 = (tid >> 4) * 4;
    const int s0 = (tid & 15) * 4;

    float acc[4][4];
    #pragma unroll
    for (int i = 0; i < 4; i++)
        #pragma unroll
        for (int q = 0; q < 4; q++) acc[i][q] = 0.f;

    const int row = tid >> 2;
    const int cb  = (tid & 3) * 32;

    for (int half = 0; half < 2; half++) {
        __syncthreads();
        #pragma unroll
        for (int d = 0; d < 8; d++) {
            float4 v = *(const float4*)(kbase + (size_t)row * HALFz + half * 128 + cb + 4 * d);
            float* w = Kh + row * 129 + cb + 4 * d;
            w[0] = v.x; w[1] = v.y; w[2] = v.z; w[3] = v.w;
        }
        __syncthreads();
        #pragma unroll 4
        for (int j = 0; j < 128; j++) {
            float a0 = Kh[(t0 + 0) * 129 + j], a1 = Kh[(t0 + 1) * 129 + j];
            float a2 = Kh[(t0 + 2) * 129 + j], a3 = Kh[(t0 + 3) * 129 + j];
            float b0 = Kh[(s0 + 0) * 129 + j], b1 = Kh[(s0 + 1) * 129 + j];
            float b2 = Kh[(s0 + 2) * 129 + j], b3 = Kh[(s0 + 3) * 129 + j];
            acc[0][0] += a0 * b0; acc[0][1] += a0 * b1; acc[0][2] += a0 * b2; acc[0][3] += a0 * b3;
            acc[1][0] += a1 * b0; acc[1][1] += a1 * b1; acc[1][2] += a1 * b2; acc[1][3] += a1 * b3;
            acc[2][0] += a2 * b0; acc[2][1] += a2 * b1; acc[2][2] += a2 * b2; acc[2][3] += a2 * b3;
            acc[3][0] += a3 * b0; acc[3][1] += a3 * b1; acc[3][2] += a3 * b2; acc[3][3] += a3 * b3;
        }
    }
    float* out = g_gram + ((size_t)(mat * Bz + b) * NCH + ch) * 4096;
    #pragma unroll
    for (int i = 0; i < 4; i++)
        #pragma unroll
        for (int q = 0; q < 4; q++)
            out[(t0 + i) * 64 + s0 + q] = acc[i][q];
}

// ---------------- chunked delta-rule scan (2 blocks/SM layout) ---------------
// smem: Ks 64KB | Q 16KB | As 16KB | Us 16KB (aliased as q-partial buf) | Bs
// grid (4 rowblocks, 2 mats, 64 batches), 256 threads (r = tid&63, g = tid>>6).
#define SCAN_SMEM ((16384 + 4096 + 4096 + 4096 + 64) * 4)

__global__ __launch_bounds__(256, 2)
void scan_k()
{
    extern __shared__ float sm[];
    float* Ks = sm;              // [64][256]
    float* Q  = Ks + 16384;      // [64][64]  reduced q0 + presums
    float* As = Q  + 4096;       // [64][64]  Gram
    float* Us = As + 4096;       // [64][64]  U  (q-phase: partial buffer [4][16][64])
    float* Bs = Us + 4096;       // [64]

    const int tid = threadIdx.x;
    const int rb  = blockIdx.x;
    const int mat = blockIdx.y;
    const int b   = blockIdx.z;
    const int r   = tid & 63;
    const int g   = tid >> 6;
    const int r0  = rb * 64;

    const float* kbase = (mat ? g_ke : g_ks) + (size_t)b * Lz * HALFz;
    const float* sv    = g_sinv + mat * Mz + b * Lz;
    const float* gbase = g_gram + (size_t)(mat * Bz + b) * NCH * 4096;

    ull M2[32];
    #pragma unroll
    for (int i = 0; i < 32; i++) M2[i] = 0ull;

    for (int ch = 0; ch < NCH; ch++) {
        const int c0   = ch * 64;
        const int clen = (ch == NCH - 1) ? 63 : 64;

        __syncthreads();                 // previous chunk done with Ks/Us
        #pragma unroll
        for (int q = 0; q < 16; q++) {
            int off = tid * 4 + q * 1024;
            *(float4*)(Ks + off) = *(const float4*)(kbase + (size_t)c0 * HALFz + off);
        }
        #pragma unroll
        for (int q = 0; q < 4; q++) {
            int off = tid * 4 + q * 1024;
            *(float4*)(As + off) = *(const float4*)(gbase + ch * 4096 + off);
        }
        if (tid < 64) Bs[tid] = sv[c0 + tid];
        __syncthreads();

        // ---- q phase in quarters of 16 t; partials staged in Us alias
        for (int qt = 0; qt < 4; qt++) {
            float p[16];
            #pragma unroll
            for (int tt = 0; tt < 16; tt++) {
                int t = qt * 16 + tt;
                ull a0 = 0ull, a1 = 0ull;
                const ull* kt2 = (const ull*)(Ks + t * 256 + g * 64);
                #pragma unroll
                for (int jj = 0; jj < 32; jj += 2) {
                    fma2(a0, M2[jj],     kt2[jj]);
                    fma2(a1, M2[jj + 1], kt2[jj + 1]);
                }
                float2 s0 = upk(a0), s1 = upk(a1);
                p[tt] = (s0.x + s0.y) + (s1.x + s1.y);
            }
            #pragma unroll
            for (int tt = 0; tt < 16; tt++)
                Us[g * 1024 + tt * 64 + r] = p[tt];
            __syncthreads();
            #pragma unroll
            for (int j = 0; j < 4; j++) {
                int tt = g * 4 + j;
                Q[(qt * 16 + tt) * 64 + r] =
                    Us[tt * 64 + r] + Us[1024 + tt * 64 + r]
                  + Us[2048 + tt * 64 + r] + Us[3072 + tt * 64 + r];
            }
            __syncthreads();
        }

        // ---- substitution: 4 sub-blocks of 16, right-looking parallel updates
        for (int sb = 0; sb < 4; sb++) {
            if (g == 0) {
                #pragma unroll 1
                for (int tt = 0; tt < 16; tt++) {
                    int t = sb * 16 + tt;
                    if (t < clen) {
                        float S = 0.f;
                        const float* At = As + t * 64;
                        for (int s = sb * 16; s < t; s++)
                            S += At[s] * Us[s * 64 + r];
                        float alpha = (mat == 0) ? 1.f
                                     : (float)(c0 + t + 1) * (1.f / 1024.f);
                        float gam = alpha * Bs[t];
                        Us[t * 64 + r] = alpha * Ks[t * 256 + r0 + r]
                                       - gam * (Q[t * 64 + r] + S);
                    }
                }
            }
            __syncthreads();
            if (sb < 3) {
                const int tstart = (sb + 1) * 16;
                const int nt = 64 - tstart;
                for (int o = tid; o < nt * 64; o += 256) {
                    int tt = tstart + (o >> 6);
                    int rr = o & 63;
                    float acc = 0.f;
                    const float* At = As + tt * 64;
                    #pragma unroll
                    for (int s = sb * 16; s < sb * 16 + 16; s++)
                        acc += At[s] * Us[s * 64 + rr];
                    Q[tt * 64 + rr] += acc;
                }
                __syncthreads();
            }
        }

        // ---- update: M += U^T K
        #pragma unroll 1
        for (int t = 0; t < clen; t++) {
            float u = Us[t * 64 + r];
            ull u2 = pk(u, u);
            const ull* kt2 = (const ull*)(Ks + t * 256 + g * 64);
            #pragma unroll
            for (int jj = 0; jj < 32; jj++) fma2(M2[jj], u2, kt2[jj]);
        }
    }

    // ---- final query: c = M . k_{L-1}
    __syncthreads();
    {
        ull a0 = 0ull, a1 = 0ull;
        const ull* kt2 = (const ull*)(Ks + 63 * 256 + g * 64);
        #pragma unroll
        for (int jj = 0; jj < 32; jj += 2) {
            fma2(a0, M2[jj],     kt2[jj]);
            fma2(a1, M2[jj + 1], kt2[jj + 1]);
        }
        float2 s0 = upk(a0), s1 = upk(a1);
        Q[g * 64 + r] = (s0.x + s0.y) + (s1.x + s1.y);
    }
    __syncthreads();
    if (g == 0)
        g_c[b * (2 * HALFz) + mat * HALFz + r0 + r] =
            Q[r] + Q[64 + r] + Q[128 + r] + Q[192 + r];
}

// ---------------- logits -----------------------------------------------------
__global__ __launch_bounds__(256)
void out_k(const float* __restrict__ W, const float* __restrict__ ob,
           float* __restrict__ out)
{
    __shared__ float sc[512][16];
    const int mt  = blockIdx.y;
    const int tid = threadIdx.x;

    for (int i = tid; i < 16 * 512; i += 256) {
        int mm = i >> 9, k = i & 511;
        sc[k][mm] = g_c[(mt * 16 + mm) * 512 + k];
    }
    __syncthreads();

    const int n = blockIdx.x * 256 + tid;
    float acc[16];
    #pragma unroll
    for (int m = 0; m < 16; m++) acc[m] = 0.f;

    #pragma unroll 8
    for (int k = 0; k < 512; k++) {
        float w = __ldg(W + (size_t)k * Vz + n);
        #pragma unroll
        for (int q = 0; q < 4; q++) {
            float4 s = *(const float4*)&sc[k][q * 4];
            acc[q * 4 + 0] += s.x * w;
            acc[q * 4 + 1] += s.y * w;
            acc[q * 4 + 2] += s.z * w;
            acc[q * 4 + 3] += s.w * w;
        }
    }
    float bb = ob[n];
    #pragma unroll
    for (int m = 0; m < 16; m++)
        out[(size_t)(mt * 16 + m) * Vz + n] = acc[m] + bb;
}

// ---------------- launch ------------------------------------------------------
extern "C" void kernel_launch(void* const* d_in, const int* in_sizes, int n_in,
                              void* d_out, int out_size)
{
    (void)in_sizes; (void)n_in; (void)out_size;
    const int*   seq    = (const int*)  d_in[0];
    const float* embed  = (const float*)d_in[1];
    const float* ff_w1  = (const float*)d_in[2];
    const float* ff_b1  = (const float*)d_in[3];
    const float* ff_w2  = (const float*)d_in[4];
    const float* ff_b2  = (const float*)d_in[5];
    const float* ln_g   = (const float*)d_in[6];
    const float* ln_b   = (const float*)d_in[7];
    const float* sem_w  = (const float*)d_in[8];
    const float* sem_b  = (const float*)d_in[9];
    const float* epi_w  = (const float*)d_in[10];
    const float* epi_b  = (const float*)d_in[11];
    const float* out_w  = (const float*)d_in[12];
    const float* out_b  = (const float*)d_in[13];
    float* out = (float*)d_out;

    cudaFuncSetAttribute(scan_k, cudaFuncAttributeMaxDynamicSharedMemorySize, SCAN_SMEM);
    cudaFuncSetAttribute(mgemm_k<0>, cudaFuncAttributeMaxDynamicSharedMemorySize, MG_SMEM);
    cudaFuncSetAttribute(mgemm_k<1>, cudaFuncAttributeMaxDynamicSharedMemorySize, MG_SMEM);
    cudaFuncSetAttribute(mgemm_k<2>, cudaFuncAttributeMaxDynamicSharedMemorySize, MG_SMEM);

    __nv_bfloat16 *w1hi, *w1lo, *w2hi, *w2lo, *swhi, *swlo, *ewhi, *ewlo;
    float *relu_p, *x_p, *h_p, *ks_p, *ke_p;
    cudaGetSymbolAddress((void**)&w1hi, g_w1hi);
    cudaGetSymbolAddress((void**)&w1lo, g_w1lo);
    cudaGetSymbolAddress((void**)&w2hi, g_w2hi);
    cudaGetSymbolAddress((void**)&w2lo, g_w2lo);
    cudaGetSymbolAddress((void**)&swhi, g_swhi);
    cudaGetSymbolAddress((void**)&swlo, g_swlo);
    cudaGetSymbolAddress((void**)&ewhi, g_ewhi);
    cudaGetSymbolAddress((void**)&ewlo, g_ewlo);
    cudaGetSymbolAddress((void**)&relu_p, g_relu);
    cudaGetSymbolAddress((void**)&x_p, g_x);
    cudaGetSymbolAddress((void**)&h_p, g_h);
    cudaGetSymbolAddress((void**)&ks_p, g_ks);
    cudaGetSymbolAddress((void**)&ke_p, g_ke);

    wsplit_k<<<dim3(1024 / 32, 512 / 32), 256>>>(ff_w1, w1hi, w1lo, 512, 1024);
    wsplit_k<<<dim3(512 / 32, 1024 / 32), 256>>>(ff_w2, w2hi, w2lo, 1024, 512);
    wsplit_k<<<dim3(256 / 32, 512 / 32), 256>>>(sem_w, swhi, swlo, 512, 256);
    wsplit_k<<<dim3(256 / 32, 512 / 32), 256>>>(epi_w, ewhi, ewlo, 512, 256);

    mgemm_k<0><<<dim3(8, 512), 256, MG_SMEM>>>(seq, embed, nullptr, w1hi, w1lo,
                                               ff_b1, relu_p, 512, 1024);
    mgemm_k<1><<<dim3(4, 512), 256, MG_SMEM>>>(seq, embed, relu_p, w2hi, w2lo,
                                               ff_b2, x_p, 1024, 512);
    ln_k<<<Mz / 8, 256>>>(ln_g, ln_b);
    mgemm_k<2><<<dim3(2, 512), 256, MG_SMEM>>>(seq, embed, h_p, swhi, swlo,
                                               sem_b, ks_p, 512, 256);
    mgemm_k<2><<<dim3(2, 512), 256, MG_SMEM>>>(seq, embed, h_p, ewhi, ewlo,
                                               epi_b, ke_p, 512, 256);
    sinv_k<<<(2 * Mz) / 8, 256>>>();
    gram_k<<<dim3(NCH, 2, Bz), 256>>>();
    scan_k<<<dim3(4, 2, Bz), 256, SCAN_SMEM>>>();
    out_k<<<dim3(125, 4), 256>>>(out_w, out_b, out);
}

// round 10
// speedup vs baseline: 3.3187x; 1.0345x over previous
#include <cuda_runtime.h>
#include <cuda_bf16.h>
#include <cstdint>

#define Bz   64
#define Lz   1024
#define Hz   512
#define HALFz 256
#define Vz   32000
#define Mz   (Bz*Lz)          /* 65536 rows */
#define NCH  16               /* chunks of 64 steps */

typedef unsigned long long ull;

// ---------------- f32x2 packed-math helpers ----------------------------------
__device__ __forceinline__ void fma2(ull &d, ull a, ull b) {
    asm("fma.rn.f32x2 %0, %1, %2, %0;" : "+l"(d) : "l"(a), "l"(b));
}
__device__ __forceinline__ ull pk(float lo, float hi) {
    ull r; asm("mov.b64 %0, {%1, %2};" : "=l"(r) : "f"(lo), "f"(hi)); return r;
}
__device__ __forceinline__ float2 upk(ull v) {
    float2 r; asm("mov.b64 {%0, %1}, %2;" : "=f"(r.x), "=f"(r.y) : "l"(v)); return r;
}

// ---------------- warp-mma helpers (arch-portable HMMA) ----------------------
__device__ __forceinline__ uint32_t smem_u32(const void* p) {
    uint32_t a;
    asm("{ .reg .u64 t; cvta.to.shared.u64 t, %1; cvt.u32.u64 %0, t; }"
        : "=r"(a) : "l"(p));
    return a;
}
__device__ __forceinline__ void ldm4(uint32_t* r, uint32_t addr) {
    asm volatile("ldmatrix.sync.aligned.m8n8.x4.shared.b16 {%0,%1,%2,%3}, [%4];"
        : "=r"(r[0]), "=r"(r[1]), "=r"(r[2]), "=r"(r[3]) : "r"(addr));
}
__device__ __forceinline__ void mma_bf16(float* c, const uint32_t* a,
                                         const uint32_t* b) {
    asm volatile("mma.sync.aligned.m16n8k16.row.col.f32.bf16.bf16.f32 "
        "{%0,%1,%2,%3}, {%4,%5,%6,%7}, {%8,%9}, {%0,%1,%2,%3};"
        : "+f"(c[0]), "+f"(c[1]), "+f"(c[2]), "+f"(c[3])
        : "r"(a[0]), "r"(a[1]), "r"(a[2]), "r"(a[3]), "r"(b[0]), "r"(b[1]));
}
__device__ __forceinline__ void cpa16(uint32_t dst, const void* src) {
    asm volatile("cp.async.ca.shared.global [%0], [%1], 16;"
                 :: "r"(dst), "l"(src) : "memory");
}
__device__ __forceinline__ void cpa_wait_all() {
    asm volatile("cp.async.wait_all;" ::: "memory");
}

// ---------------- scratch ----------------------------------------------------
__device__ float g_relu[(size_t)Mz * 1024];
__device__ float g_x   [(size_t)Mz * Hz];
__device__ float g_h   [(size_t)Mz * Hz];
__device__ float g_ks  [(size_t)Mz * HALFz];
__device__ float g_ke  [(size_t)Mz * HALFz];
__device__ float g_sinv[2 * Mz];
__device__ float g_gram[(size_t)2 * Bz * NCH * 64 * 64];
__device__ float g_c   [Bz * 2 * HALFz];
__device__ __nv_bfloat16 g_w1hi[1024 * 512], g_w1lo[1024 * 512];
__device__ __nv_bfloat16 g_w2hi[512 * 1024], g_w2lo[512 * 1024];
__device__ __nv_bfloat16 g_swhi[256 * 512],  g_swlo[256 * 512];
__device__ __nv_bfloat16 g_ewhi[256 * 512],  g_ewlo[256 * 512];

// ---------------- weight transpose + bf16 split:  W[K][N] -> [N][K] hi/lo ----
__global__ __launch_bounds__(256)
void wsplit_k(const float* __restrict__ W, __nv_bfloat16* __restrict__ hi,
              __nv_bfloat16* __restrict__ lo, int K, int N)
{
    __shared__ float t[32][33];
    const int n0 = blockIdx.x * 32, k0 = blockIdx.y * 32;
    const int tx = threadIdx.x & 31, ty = threadIdx.x >> 5;
    #pragma unroll
    for (int p = 0; p < 4; p++) {
        int kk = ty + p * 8;
        t[kk][tx] = W[(size_t)(k0 + kk) * N + n0 + tx];
    }
    __syncthreads();
    #pragma unroll
    for (int p = 0; p < 4; p++) {
        int r = ty + p * 8;
        float v = t[tx][r];
        __nv_bfloat16 h = __float2bfloat16(v);
        __nv_bfloat16 l = __float2bfloat16(v - __bfloat162float(h));
        size_t o = (size_t)(n0 + r) * K + k0 + tx;
        hi[o] = h; lo[o] = l;
    }
}

// ---------------- HMMA split-bf16 GEMM ---------------------------------------
// 128x128 block, BK=32, 8 warps (4m x 2n), warp tile 32x64, m16n8k16.
#define MG_STR  40                       /* bf16 per smem row (32 + 8 pad)   */
#define MG_AH   0
#define MG_AL   (128 * MG_STR)
#define MG_BH   (2 * 128 * MG_STR)
#define MG_BL   (3 * 128 * MG_STR)
#define MG_STAGE (4 * 128 * MG_STR)      /* bf16 units = 20480               */
#define MG_SMEM (2 * MG_STAGE * 2)       /* bytes = 81920                    */

template<int MODE>
__global__ __launch_bounds__(256, 2)
void mgemm_k(const int* __restrict__ seq, const float* __restrict__ embed,
             const float* __restrict__ Afp,
             const __nv_bfloat16* __restrict__ Bhi,
             const __nv_bfloat16* __restrict__ Blo,
             const float* __restrict__ bias, float* __restrict__ Cout,
             int Kfull, int Nfull)
{
    extern __shared__ __nv_bfloat16 smb[];
    __shared__ int seqs[128];

    const int tid  = threadIdx.x;
    const int lane = tid & 31;
    const int wid  = tid >> 5;
    const int wm   = wid & 3;            // 0..3: m-tile of 32 rows
    const int wn   = wid >> 2;           // 0..1: n-tile of 64 cols
    const int m0 = blockIdx.y * 128;
    const int n0 = blockIdx.x * 128;

    if (MODE != 2 && tid < 128) seqs[tid] = seq[m0 + tid];
    __syncthreads();

    float acc[2][8][4];
    #pragma unroll
    for (int i = 0; i < 2; i++)
        #pragma unroll
        for (int n = 0; n < 8; n++)
            #pragma unroll
            for (int q = 0; q < 4; q++) acc[i][n][q] = 0.f;

    const int nk = Kfull >> 5;           // BK = 32

    // stage loader: A through registers (fp32->hi/lo split), B via cp.async
    auto mg_load = [&](int kc, int s) {
        __nv_bfloat16* sb = smb + s * MG_STAGE;
        const int k0 = kc << 5;
        {   // B: pre-split bf16 [N][K] — async 16B copies
            const uint32_t sbu = smem_u32(sb);
            const int row0 = tid >> 2;
            const int k8   = (tid & 3) << 3;
            #pragma unroll
            for (int p = 0; p < 2; p++) {
                int n = row0 + p * 64;
                size_t o = (size_t)(n0 + n) * Kfull + k0 + k8;
                int d = n * MG_STR + k8;
                cpa16(sbu + (MG_BH + d) * 2, Bhi + o);
                cpa16(sbu + (MG_BL + d) * 2, Blo + o);
            }
        }
        {   // A: fp32 -> hi/lo
            const int row0 = tid >> 3;
            const int k4   = (tid & 7) << 2;
            #pragma unroll
            for (int p = 0; p < 4; p++) {
                int row = row0 + p * 32;
                const float* src;
                if (MODE == 0) src = embed + (size_t)seqs[row] * Hz + k0 + k4;
                else           src = Afp + (size_t)(m0 + row) * Kfull + k0 + k4;
                float4 v = *(const float4*)src;
                __nv_bfloat162 h01 = __floats2bfloat162_rn(v.x, v.y);
                __nv_bfloat162 h23 = __floats2bfloat162_rn(v.z, v.w);
                __nv_bfloat162 l01 = __floats2bfloat162_rn(
                    v.x - __bfloat162float(h01.x), v.y - __bfloat162float(h01.y));
                __nv_bfloat162 l23 = __floats2bfloat162_rn(
                    v.z - __bfloat162float(h23.x), v.w - __bfloat162float(h23.y));
                int o = row * MG_STR + k4;
                *(uint2*)(sb + MG_AH + o) = make_uint2(*(uint32_t*)&h01, *(uint32_t*)&h23);
                *(uint2*)(sb + MG_AL + o) = make_uint2(*(uint32_t*)&l01, *(uint32_t*)&l23);
            }
        }
    };

    mg_load(0, 0);
    cpa_wait_all();
    __syncthreads();

    for (int kc = 0; kc < nk; kc++) {
        if (kc + 1 < nk) mg_load(kc + 1, (kc + 1) & 1);

        const __nv_bfloat16* sb = smb + (kc & 1) * MG_STAGE;
        const uint32_t aH = smem_u32(sb + MG_AH);
        const uint32_t aL = smem_u32(sb + MG_AL);
        const uint32_t bH = smem_u32(sb + MG_BH);
        const uint32_t bL = smem_u32(sb + MG_BL);

        #pragma unroll
        for (int ks = 0; ks < 2; ks++) {
            uint32_t ah[2][4], al[2][4];
            const int ar = wm * 32 + (lane & 15);
            const int ac = ks * 16 + ((lane >> 4) << 3);
            #pragma unroll
            for (int i = 0; i < 2; i++) {
                uint32_t off = ((ar + i * 16) * MG_STR + ac) * 2;
                ldm4(ah[i], aH + off);
                ldm4(al[i], aL + off);
            }
            #pragma unroll
            for (int j = 0; j < 4; j++) {
                const int nr = wn * 64 + j * 16 + (lane & 7) + ((lane >> 4) << 3);
                const int kc2 = ks * 16 + (((lane >> 3) & 1) << 3);
                uint32_t off = (nr * MG_STR + kc2) * 2;
                uint32_t bh[4], bl[4];
                ldm4(bh, bH + off);
                ldm4(bl, bL + off);
                #pragma unroll
                for (int i = 0; i < 2; i++) {
                    mma_bf16(acc[i][2 * j],     ah[i], bh);
                    mma_bf16(acc[i][2 * j + 1], ah[i], bh + 2);
                    mma_bf16(acc[i][2 * j],     ah[i], bl);
                    mma_bf16(acc[i][2 * j + 1], ah[i], bl + 2);
                    mma_bf16(acc[i][2 * j],     al[i], bh);
                    mma_bf16(acc[i][2 * j + 1], al[i], bh + 2);
                }
            }
        }
        cpa_wait_all();
        __syncthreads();
    }

    // epilogue
    #pragma unroll
    for (int i = 0; i < 2; i++) {
        int rlo = wm * 32 + i * 16 + (lane >> 2);
        #pragma unroll
        for (int n = 0; n < 8; n++) {
            int col = n0 + wn * 64 + n * 8 + (lane & 3) * 2;
            float b0 = bias[col], b1 = bias[col + 1];
            #pragma unroll
            for (int h = 0; h < 2; h++) {
                int rr = rlo + h * 8;
                size_t m = m0 + rr;
                float2 o;
                o.x = acc[i][n][2 * h + 0] + b0;
                o.y = acc[i][n][2 * h + 1] + b1;
                if (MODE == 0) { o.x = fmaxf(o.x, 0.f); o.y = fmaxf(o.y, 0.f); }
                if (MODE == 1) {
                    const float* e = embed + (size_t)seqs[rr] * Hz + col;
                    o.x += e[0]; o.y += e[1];
                }
                *(float2*)(Cout + m * Nfull + col) = o;
            }
        }
    }
}

// ---------------- LayerNorm --------------------------------------------------
__global__ __launch_bounds__(256)
void ln_k(const float* __restrict__ gam, const float* __restrict__ bet)
{
    int row  = blockIdx.x * 8 + (threadIdx.x >> 5);
    int lane = threadIdx.x & 31;
    const float* x = g_x + (size_t)row * Hz;

    float4 v[4];
    float sum = 0.f, sq = 0.f;
    #pragma unroll
    for (int i = 0; i < 4; i++) {
        v[i] = *(const float4*)(x + lane * 4 + i * 128);
        sum += v[i].x + v[i].y + v[i].z + v[i].w;
        sq  += v[i].x * v[i].x + v[i].y * v[i].y + v[i].z * v[i].z + v[i].w * v[i].w;
    }
    #pragma unroll
    for (int off = 16; off > 0; off >>= 1) {
        sum += __shfl_xor_sync(0xffffffffu, sum, off);
        sq  += __shfl_xor_sync(0xffffffffu, sq,  off);
    }
    float mean = sum * (1.f / 512.f);
    float var  = sq  * (1.f / 512.f) - mean * mean;
    float rs   = rsqrtf(var + 1e-5f);

    float* o = g_h + (size_t)row * Hz;
    #pragma unroll
    for (int i = 0; i < 4; i++) {
        int col = lane * 4 + i * 128;
        float4 gg = *(const float4*)(gam + col);
        float4 bb = *(const float4*)(bet + col);
        float4 r;
        r.x = (v[i].x - mean) * rs * gg.x + bb.x;
        r.y = (v[i].y - mean) * rs * gg.y + bb.y;
        r.z = (v[i].z - mean) * rs * gg.z + bb.z;
        r.w = (v[i].w - mean) * rs * gg.w + bb.w;
        *(float4*)(o + col) = r;
    }
}

// ---------------- per-chunk Gram (fused 1/(k.k+eps) on the diagonal) ---------
__global__ __launch_bounds__(256)
void gram_k()
{
    __shared__ float Kh[64 * 129];
    const int ch = blockIdx.x, mat = blockIdx.y, b = blockIdx.z;
    const float* kbase = (mat ? g_ke : g_ks)
                         + (size_t)b * Lz * HALFz + (size_t)ch * 64 * HALFz;
    const int tid = threadIdx.x;
    const int t0 = (tid >> 4) * 4;
    const int s0 = (tid & 15) * 4;

    float acc[4][4];
    #pragma unroll
    for (int i = 0; i < 4; i++)
        #pragma unroll
        for (int q = 0; q < 4; q++) acc[i][q] = 0.f;

    const int row = tid >> 2;
    const int cb  = (tid & 3) * 32;

    for (int half = 0; half < 2; half++) {
        __syncthreads();
        #pragma unroll
        for (int d = 0; d < 8; d++) {
            float4 v = *(const float4*)(kbase + (size_t)row * HALFz + half * 128 + cb + 4 * d);
            float* w = Kh + row * 129 + cb + 4 * d;
            w[0] = v.x; w[1] = v.y; w[2] = v.z; w[3] = v.w;
        }
        __syncthreads();
        #pragma unroll 4
        for (int j = 0; j < 128; j++) {
            float a0 = Kh[(t0 + 0) * 129 + j], a1 = Kh[(t0 + 1) * 129 + j];
            float a2 = Kh[(t0 + 2) * 129 + j], a3 = Kh[(t0 + 3) * 129 + j];
            float b0 = Kh[(s0 + 0) * 129 + j], b1 = Kh[(s0 + 1) * 129 + j];
            float b2 = Kh[(s0 + 2) * 129 + j], b3 = Kh[(s0 + 3) * 129 + j];
            acc[0][0] += a0 * b0; acc[0][1] += a0 * b1; acc[0][2] += a0 * b2; acc[0][3] += a0 * b3;
            acc[1][0] += a1 * b0; acc[1][1] += a1 * b1; acc[1][2] += a1 * b2; acc[1][3] += a1 * b3;
            acc[2][0] += a2 * b0; acc[2][1] += a2 * b1; acc[2][2] += a2 * b2; acc[2][3] += a2 * b3;
            acc[3][0] += a3 * b0; acc[3][1] += a3 * b1; acc[3][2] += a3 * b2; acc[3][3] += a3 * b3;
        }
    }
    float* out = g_gram + ((size_t)(mat * Bz + b) * NCH + ch) * 4096;
    #pragma unroll
    for (int i = 0; i < 4; i++)
        #pragma unroll
        for (int q = 0; q < 4; q++)
            out[(t0 + i) * 64 + s0 + q] = acc[i][q];

    if (t0 == s0) {   // diagonal owner: beta = 1/(k.k + eps), k.k = A[t][t]
        float* sv = g_sinv + mat * Mz + b * Lz + ch * 64;
        #pragma unroll
        for (int i = 0; i < 4; i++)
            sv[t0 + i] = 1.f / (acc[i][i] + 1e-6f);
    }
}

// ---------------- chunked delta-rule scan (LDS.128 k loads) ------------------
#define SCAN_SMEM ((16384 + 4096 + 4096 + 4096 + 64) * 4)

__global__ __launch_bounds__(256, 2)
void scan_k()
{
    extern __shared__ float sm[];
    float* Ks = sm;              // [64][256]
    float* Q  = Ks + 16384;      // [64][64]  reduced q0 + presums
    float* As = Q  + 4096;       // [64][64]  Gram
    float* Us = As + 4096;       // [64][64]  U  (q-phase: partial buffer)
    float* Bs = Us + 4096;       // [64]

    const int tid = threadIdx.x;
    const int rb  = blockIdx.x;
    const int mat = blockIdx.y;
    const int b   = blockIdx.z;
    const int r   = tid & 63;
    const int g   = tid >> 6;
    const int r0  = rb * 64;

    const float* kbase = (mat ? g_ke : g_ks) + (size_t)b * Lz * HALFz;
    const float* sv    = g_sinv + mat * Mz + b * Lz;
    const float* gbase = g_gram + (size_t)(mat * Bz + b) * NCH * 4096;

    ull M2[32];
    #pragma unroll
    for (int i = 0; i < 32; i++) M2[i] = 0ull;

    for (int ch = 0; ch < NCH; ch++) {
        const int c0   = ch * 64;
        const int clen = (ch == NCH - 1) ? 63 : 64;

        __syncthreads();                 // previous chunk done with Ks/Us
        #pragma unroll
        for (int q = 0; q < 16; q++) {
            int off = tid * 4 + q * 1024;
            *(float4*)(Ks + off) = *(const float4*)(kbase + (size_t)c0 * HALFz + off);
        }
        #pragma unroll
        for (int q = 0; q < 4; q++) {
            int off = tid * 4 + q * 1024;
            *(float4*)(As + off) = *(const float4*)(gbase + ch * 4096 + off);
        }
        if (tid < 64) Bs[tid] = sv[c0 + tid];
        __syncthreads();

        // ---- q phase in quarters of 16 t; partials staged in Us alias
        for (int qt = 0; qt < 4; qt++) {
            float p[16];
            #pragma unroll
            for (int tt = 0; tt < 16; tt++) {
                int t = qt * 16 + tt;
                ull a0 = 0ull, a1 = 0ull;
                const ulonglong2* kt4 = (const ulonglong2*)(Ks + t * 256 + g * 64);
                #pragma unroll
                for (int jj = 0; jj < 16; jj++) {
                    ulonglong2 kv = kt4[jj];
                    fma2(a0, M2[2 * jj],     kv.x);
                    fma2(a1, M2[2 * jj + 1], kv.y);
                }
                float2 s0 = upk(a0), s1 = upk(a1);
                p[tt] = (s0.x + s0.y) + (s1.x + s1.y);
            }
            #pragma unroll
            for (int tt = 0; tt < 16; tt++)
                Us[g * 1024 + tt * 64 + r] = p[tt];
            __syncthreads();
            #pragma unroll
            for (int j = 0; j < 4; j++) {
                int tt = g * 4 + j;
                Q[(qt * 16 + tt) * 64 + r] =
                    Us[tt * 64 + r] + Us[1024 + tt * 64 + r]
                  + Us[2048 + tt * 64 + r] + Us[3072 + tt * 64 + r];
            }
            __syncthreads();
        }

        // ---- substitution: 4 sub-blocks of 16, right-looking parallel updates
        for (int sb = 0; sb < 4; sb++) {
            if (g == 0) {
                #pragma unroll 1
                for (int tt = 0; tt < 16; tt++) {
                    int t = sb * 16 + tt;
                    if (t < clen) {
                        float S = 0.f;
                        const float* At = As + t * 64;
                        for (int s = sb * 16; s < t; s++)
                            S += At[s] * Us[s * 64 + r];
                        float alpha = (mat == 0) ? 1.f
                                     : (float)(c0 + t + 1) * (1.f / 1024.f);
                        float gam = alpha * Bs[t];
                        Us[t * 64 + r] = alpha * Ks[t * 256 + r0 + r]
                                       - gam * (Q[t * 64 + r] + S);
                    }
                }
            }
            __syncthreads();
            if (sb < 3) {
                const int tstart = (sb + 1) * 16;
                const int nt = 64 - tstart;
                for (int o = tid; o < nt * 64; o += 256) {
                    int tt = tstart + (o >> 6);
                    int rr = o & 63;
                    float acc = 0.f;
                    const float* At = As + tt * 64;
                    #pragma unroll
                    for (int s = sb * 16; s < sb * 16 + 16; s++)
                        acc += At[s] * Us[s * 64 + rr];
                    Q[tt * 64 + rr] += acc;
                }
                __syncthreads();
            }
        }

        // ---- update: M += U^T K  (LDS.128 k loads)
        #pragma unroll 1
        for (int t = 0; t < clen; t++) {
            float u = Us[t * 64 + r];
            ull u2 = pk(u, u);
            const ulonglong2* kt4 = (const ulonglong2*)(Ks + t * 256 + g * 64);
            #pragma unroll
            for (int jj = 0; jj < 16; jj++) {
                ulonglong2 kv = kt4[jj];
                fma2(M2[2 * jj],     u2, kv.x);
                fma2(M2[2 * jj + 1], u2, kv.y);
            }
        }
    }

    // ---- final query: c = M . k_{L-1}
    __syncthreads();
    {
        ull a0 = 0ull, a1 = 0ull;
        const ulonglong2* kt4 = (const ulonglong2*)(Ks + 63 * 256 + g * 64);
        #pragma unroll
        for (int jj = 0; jj < 16; jj++) {
            ulonglong2 kv = kt4[jj];
            fma2(a0, M2[2 * jj],     kv.x);
            fma2(a1, M2[2 * jj + 1], kv.y);
        }
        float2 s0 = upk(a0), s1 = upk(a1);
        Q[g * 64 + r] = (s0.x + s0.y) + (s1.x + s1.y);
    }
    __syncthreads();
    if (g == 0)
        g_c[b * (2 * HALFz) + mat * HALFz + r0 + r] =
            Q[r] + Q[64 + r] + Q[128 + r] + Q[192 + r];
}

// ---------------- logits -----------------------------------------------------
__global__ __launch_bounds__(256)
void out_k(const float* __restrict__ W, const float* __restrict__ ob,
           float* __restrict__ out)
{
    __shared__ float sc[512][16];
    const int mt  = blockIdx.y;
    const int tid = threadIdx.x;

    for (int i = tid; i < 16 * 512; i += 256) {
        int mm = i >> 9, k = i & 511;
        sc[k][mm] = g_c[(mt * 16 + mm) * 512 + k];
    }
    __syncthreads();

    const int n = blockIdx.x * 256 + tid;
    float acc[16];
    #pragma unroll
    for (int m = 0; m < 16; m++) acc[m] = 0.f;

    #pragma unroll 8
    for (int k = 0; k < 512; k++) {
        float w = __ldg(W + (size_t)k * Vz + n);
        #pragma unroll
        for (int q = 0; q < 4; q++) {
            float4 s = *(const float4*)&sc[k][q * 4];
            acc[q * 4 + 0] += s.x * w;
            acc[q * 4 + 1] += s.y * w;
            acc[q * 4 + 2] += s.z * w;
            acc[q * 4 + 3] += s.w * w;
        }
    }
    float bb = ob[n];
    #pragma unroll
    for (int m = 0; m < 16; m++)
        out[(size_t)(mt * 16 + m) * Vz + n] = acc[m] + bb;
}

// ---------------- launch ------------------------------------------------------
extern "C" void kernel_launch(void* const* d_in, const int* in_sizes, int n_in,
                              void* d_out, int out_size)
{
    (void)in_sizes; (void)n_in; (void)out_size;
    const int*   seq    = (const int*)  d_in[0];
    const float* embed  = (const float*)d_in[1];
    const float* ff_w1  = (const float*)d_in[2];
    const float* ff_b1  = (const float*)d_in[3];
    const float* ff_w2  = (const float*)d_in[4];
    const float* ff_b2  = (const float*)d_in[5];
    const float* ln_g   = (const float*)d_in[6];
    const float* ln_b   = (const float*)d_in[7];
    const float* sem_w  = (const float*)d_in[8];
    const float* sem_b  = (const float*)d_in[9];
    const float* epi_w  = (const float*)d_in[10];
    const float* epi_b  = (const float*)d_in[11];
    const float* out_w  = (const float*)d_in[12];
    const float* out_b  = (const float*)d_in[13];
    float* out = (float*)d_out;

    cudaFuncSetAttribute(scan_k, cudaFuncAttributeMaxDynamicSharedMemorySize, SCAN_SMEM);
    cudaFuncSetAttribute(mgemm_k<0>, cudaFuncAttributeMaxDynamicSharedMemorySize, MG_SMEM);
    cudaFuncSetAttribute(mgemm_k<1>, cudaFuncAttributeMaxDynamicSharedMemorySize, MG_SMEM);
    cudaFuncSetAttribute(mgemm_k<2>, cudaFuncAttributeMaxDynamicSharedMemorySize, MG_SMEM);

    __nv_bfloat16 *w1hi, *w1lo, *w2hi, *w2lo, *swhi, *swlo, *ewhi, *ewlo;
    float *relu_p, *x_p, *h_p, *ks_p, *ke_p;
    cudaGetSymbolAddress((void**)&w1hi, g_w1hi);
    cudaGetSymbolAddress((void**)&w1lo, g_w1lo);
    cudaGetSymbolAddress((void**)&w2hi, g_w2hi);
    cudaGetSymbolAddress((void**)&w2lo, g_w2lo);
    cudaGetSymbolAddress((void**)&swhi, g_swhi);
    cudaGetSymbolAddress((void**)&swlo, g_swlo);
    cudaGetSymbolAddress((void**)&ewhi, g_ewhi);
    cudaGetSymbolAddress((void**)&ewlo, g_ewlo);
    cudaGetSymbolAddress((void**)&relu_p, g_relu);
    cudaGetSymbolAddress((void**)&x_p, g_x);
    cudaGetSymbolAddress((void**)&h_p, g_h);
    cudaGetSymbolAddress((void**)&ks_p, g_ks);
    cudaGetSymbolAddress((void**)&ke_p, g_ke);

    wsplit_k<<<dim3(1024 / 32, 512 / 32), 256>>>(ff_w1, w1hi, w1lo, 512, 1024);
    wsplit_k<<<dim3(512 / 32, 1024 / 32), 256>>>(ff_w2, w2hi, w2lo, 1024, 512);
    wsplit_k<<<dim3(256 / 32, 512 / 32), 256>>>(sem_w, swhi, swlo, 512, 256);
    wsplit_k<<<dim3(256 / 32, 512 / 32), 256>>>(epi_w, ewhi, ewlo, 512, 256);

    mgemm_k<0><<<dim3(8, 512), 256, MG_SMEM>>>(seq, embed, nullptr, w1hi, w1lo,
                                               ff_b1, relu_p, 512, 1024);
    mgemm_k<1><<<dim3(4, 512), 256, MG_SMEM>>>(seq, embed, relu_p, w2hi, w2lo,
                                               ff_b2, x_p, 1024, 512);
    ln_k<<<Mz / 8, 256>>>(ln_g, ln_b);
    mgemm_k<2><<<dim3(2, 512), 256, MG_SMEM>>>(seq, embed, h_p, swhi, swlo,
                                               sem_b, ks_p, 512, 256);
    mgemm_k<2><<<dim3(2, 512), 256, MG_SMEM>>>(seq, embed, h_p, ewhi, ewlo,
                                               epi_b, ke_p, 512, 256);
    gram_k<<<dim3(NCH, 2, Bz), 256>>>();
    scan_k<<<dim3(4, 2, Bz), 256, SCAN_SMEM>>>();
    out_k<<<dim3(125, 4), 256>>>(out_w, out_b, out);
}